// round 14
// baseline (speedup 1.0000x reference)
#include <cuda_runtime.h>
#include <cuda_bf16.h>
#include <cstdint>

#define BB 64
#define NN 2048
#define DD 512
#define KK 64
#define KGC 80

// Scratch (device globals — no allocation allowed)
__device__ __align__(16) __nv_bfloat16 g_aThi[(size_t)BB * KK * NN]; // assignT hi [b][k][n]
__device__ __align__(16) __nv_bfloat16 g_aTlo[(size_t)BB * KK * NN]; // assignT lo
__device__ float g_vpart[(size_t)BB * KK * DD];
__device__ float g_asum[BB * KK];
__device__ float g_norm2[BB * KK];
__device__ __align__(16) __nv_bfloat16 g_cHi[DD * KGC];
__device__ __align__(16) __nv_bfloat16 g_cLo[DD * KGC];
__device__ float g_c2T[KK * DD];

// ===================== helpers =====================
__device__ __forceinline__ uint32_t smem_to_u32(const void* p) {
    uint32_t a;
    asm("{ .reg .u64 t; cvta.to.shared.u64 t, %1; cvt.u32.u64 %0, t; }" : "=r"(a) : "l"(p));
    return a;
}
__device__ __forceinline__ void mma_bf16(float* c, const uint32_t* a, const uint32_t* b) {
    asm volatile("mma.sync.aligned.m16n8k16.row.col.f32.bf16.bf16.f32 "
        "{%0,%1,%2,%3}, {%4,%5,%6,%7}, {%8,%9}, {%0,%1,%2,%3};"
        : "+f"(c[0]), "+f"(c[1]), "+f"(c[2]), "+f"(c[3])
        : "r"(a[0]), "r"(a[1]), "r"(a[2]), "r"(a[3]), "r"(b[0]), "r"(b[1]));
}
__device__ __forceinline__ void ldsm_x4(uint32_t* r, uint32_t addr) {
    asm volatile("ldmatrix.sync.aligned.m8n8.x4.shared.b16 {%0,%1,%2,%3}, [%4];"
        : "=r"(r[0]), "=r"(r[1]), "=r"(r[2]), "=r"(r[3]) : "r"(addr));
}
__device__ __forceinline__ void ldsm_x4t(uint32_t* r, uint32_t addr) {
    asm volatile("ldmatrix.sync.aligned.m8n8.x4.trans.shared.b16 {%0,%1,%2,%3}, [%4];"
        : "=r"(r[0]), "=r"(r[1]), "=r"(r[2]), "=r"(r[3]) : "r"(addr));
}
__device__ __forceinline__ void ldsm_x2t(uint32_t* r, uint32_t addr) {
    asm volatile("ldmatrix.sync.aligned.m8n8.x2.trans.shared.b16 {%0,%1}, [%2];"
        : "=r"(r[0]), "=r"(r[1]) : "r"(addr));
}
__device__ __forceinline__ void split2(float2 v, uint32_t& hi, uint32_t& lo) {
    __nv_bfloat162 h = __float22bfloat162_rn(v);
    float2 hf = __bfloat1622float2(h);
    __nv_bfloat162 l = __float22bfloat162_rn(make_float2(v.x - hf.x, v.y - hf.y));
    hi = *(uint32_t*)&h;
    lo = *(uint32_t*)&l;
}
#define CP_ASYNC16(dst, src) \
    asm volatile("cp.async.cg.shared.global [%0], [%1], 16;" :: "r"(dst), "l"(src) : "memory")
#define CP_COMMIT() asm volatile("cp.async.commit_group;" ::: "memory")
#define CP_WAIT1()  asm volatile("cp.async.wait_group 1;" ::: "memory")
#define CP_WAIT0()  asm volatile("cp.async.wait_group 0;" ::: "memory")

// ---------------------------------------------------------------------------
// Kernel P1: split clusters to bf16 hi/lo + zero accumulators
// ---------------------------------------------------------------------------
__global__ void k_prep(const float* __restrict__ clusters) {
    int i = blockIdx.x * 256 + threadIdx.x;
    if (i < DD * KGC) {
        float v = clusters[i];
        __nv_bfloat16 h = __float2bfloat16(v);
        g_cHi[i] = h;
        g_cLo[i] = __float2bfloat16(v - __bfloat162float(h));
    }
    if (i < BB * KK) { g_asum[i] = 0.0f; g_norm2[i] = 0.0f; }
}
// Kernel P2: transpose clusters2 [512][64] -> [64][512]
__global__ void k_prep2(const float* __restrict__ clusters2) {
    int k = blockIdx.x;
    int d = threadIdx.x;
    g_c2T[k * DD + d] = clusters2[d * KK + k];
}

// ---------------------------------------------------------------------------
// Kernel 1: logits GEMM (mma.sync bf16x3) + BN + softmax + a_sum + assignT
// CTA: 256 threads = 8 warps, 4 M x 2 N. Tile M=128 x N=80, K=512 in 16
// stages of 32 d. A: 2-buffer register prefetch. B: 3-buffer cp.async,
// 2 stages in flight (wait_group 1).
// ---------------------------------------------------------------------------
// A buffers: 2 x 20480 (AH @0, AL @10240) -> [0, 40960)
// B buffers: 3 x 11264 (BH @0, BL @5632)  -> [40960, 74752)
#define LA_SZ 20480
#define LA_AL 10240
#define LB_BASE 40960
#define LB3_SZ 11264
#define LB_BL 5632
#define L_BN  74752      // 240 floats
#define L_AS  75712      // 256 floats
#define L_PM  76736      // 256 floats
#define L_PS  77760      // 256 floats
#define L_SMEM 78784

__global__ __launch_bounds__(256, 2) void k_logits_mma(
    const float* __restrict__ x,
    const float* __restrict__ bnw, const float* __restrict__ bnb,
    const float* __restrict__ rm, const float* __restrict__ rv)
{
    extern __shared__ __align__(16) char smem[];
    const int tid = threadIdx.x;
    const int lane = tid & 31, w = tid >> 5;
    const int wm = w & 3, wn = w >> 2;           // 4 M-warps x 2 N-warps
    const int b = blockIdx.y, n0 = blockIdx.x * 128;
    const float* xb = x + ((size_t)b * NN + n0) * DD;
    uint32_t sb32 = smem_to_u32(smem);

    float* sScale = (float*)(smem + L_BN);
    float* sRm = sScale + 80;
    float* sBb = sScale + 160;
    if (tid < KGC) {
        sScale[tid] = bnw[tid] * rsqrtf(rv[tid] + 1e-5f);
        sRm[tid] = rm[tid];
        sBb[tid] = bnb[tid];
    }

    float acc[2][5][4];
    #pragma unroll
    for (int mt = 0; mt < 2; mt++)
        #pragma unroll
        for (int nt = 0; nt < 5; nt++)
            #pragma unroll
            for (int e = 0; e < 4; e++) acc[mt][nt][e] = 0.f;

    const int xr_r = tid >> 3, xr_u = tid & 7;
    const int br0 = tid / 10, bc0 = tid - br0 * 10;
    const int bidx1 = tid + 256;
    const int u1 = bidx1 >= 320 ? bidx1 - 320 : bidx1;
    const int barr1 = bidx1 >= 320;
    const int br1 = u1 / 10, bc1 = u1 - br1 * 10;
    const int u2 = tid + 512 - 320;
    const int br2 = u2 / 10, bc2 = u2 - br2 * 10;
    const bool bp2 = tid < 128;

    auto cp_b = [&](int stage) {
        uint32_t base = sb32 + LB_BASE + (uint32_t)((stage % 3) * LB3_SZ);
        const __nv_bfloat16* s0 = g_cHi + (size_t)(stage * 32 + br0) * KGC + bc0 * 8;
        CP_ASYNC16(base + br0 * 176 + bc0 * 16, s0);
        const __nv_bfloat16* s1 = (barr1 ? g_cLo : g_cHi) + (size_t)(stage * 32 + br1) * KGC + bc1 * 8;
        CP_ASYNC16(base + (barr1 ? LB_BL : 0) + br1 * 176 + bc1 * 16, s1);
        if (bp2) {
            const __nv_bfloat16* s2 = g_cLo + (size_t)(stage * 32 + br2) * KGC + bc2 * 8;
            CP_ASYNC16(base + LB_BL + br2 * 176 + bc2 * 16, s2);
        }
        CP_COMMIT();
    };

    float4 xr[4];
    cp_b(0);
    cp_b(1);
    #pragma unroll
    for (int j = 0; j < 4; j++)
        xr[j] = *(const float4*)&xb[(size_t)(xr_r + j * 32) * DD + xr_u * 4];

    for (int dt = 0; dt < 16; dt++) {
        char* buf = smem + (dt & 1) * LA_SZ;
        #pragma unroll
        for (int j = 0; j < 4; j++) {
            uint32_t h0, l0, h1, l1;
            split2(make_float2(xr[j].x, xr[j].y), h0, l0);
            split2(make_float2(xr[j].z, xr[j].w), h1, l1);
            int off = (xr_r + j * 32) * 80 + xr_u * 8;
            *(uint2*)(buf + off) = make_uint2(h0, h1);
            *(uint2*)(buf + LA_AL + off) = make_uint2(l0, l1);
        }
        if (dt < 15) {
            #pragma unroll
            for (int j = 0; j < 4; j++)
                xr[j] = *(const float4*)&xb[(size_t)(xr_r + j * 32) * DD +
                                            (dt + 1) * 32 + xr_u * 4];
        }
        if (dt < 15) CP_WAIT1(); else CP_WAIT0();   // group dt complete
        __syncthreads();
        if (dt + 2 < 16) cp_b(dt + 2);

        uint32_t abase = sb32 + (uint32_t)((dt & 1) * LA_SZ);
        uint32_t bbase = sb32 + LB_BASE + (uint32_t)((dt % 3) * LB3_SZ);
        #pragma unroll
        for (int kt = 0; kt < 2; kt++) {
            uint32_t ah[2][4], al[2][4];
            #pragma unroll
            for (int mt = 0; mt < 2; mt++) {
                uint32_t aoff = (uint32_t)((wm * 32 + mt * 16 + (lane & 15)) * 80 +
                                           (kt * 16 + (lane >> 4) * 8) * 2);
                ldsm_x4(ah[mt], abase + aoff);
                ldsm_x4(al[mt], abase + LA_AL + aoff);
            }
            uint32_t bh[5][2], bl[5][2];
            #pragma unroll
            for (int p = 0; p < 2; p++) {
                uint32_t t[4];
                uint32_t boff = (uint32_t)((kt * 16 + (lane & 15)) * 176 +
                                           (wn * 40 + p * 16 + (lane >> 4) * 8) * 2);
                ldsm_x4t(t, bbase + boff);
                bh[2*p][0] = t[0]; bh[2*p][1] = t[1];
                bh[2*p+1][0] = t[2]; bh[2*p+1][1] = t[3];
                ldsm_x4t(t, bbase + LB_BL + boff);
                bl[2*p][0] = t[0]; bl[2*p][1] = t[1];
                bl[2*p+1][0] = t[2]; bl[2*p+1][1] = t[3];
            }
            {
                uint32_t boff = (uint32_t)((kt * 16 + (lane & 15)) * 176 + (wn * 40 + 32) * 2);
                ldsm_x2t(bh[4], bbase + boff);
                ldsm_x2t(bl[4], bbase + LB_BL + boff);
            }
            #pragma unroll
            for (int nt = 0; nt < 5; nt++)
                #pragma unroll
                for (int mt = 0; mt < 2; mt++) {
                    mma_bf16(acc[mt][nt], ah[mt], bh[nt]);
                    mma_bf16(acc[mt][nt], ah[mt], bl[nt]);
                    mma_bf16(acc[mt][nt], al[mt], bh[nt]);
                }
        }
    }
    __syncthreads();

    // ---- BN affine ----
    #pragma unroll
    for (int nt = 0; nt < 5; nt++) {
        int c0 = wn * 40 + nt * 8 + (lane & 3) * 2;
        float s0 = sScale[c0], s1 = sScale[c0 + 1];
        float m0 = sRm[c0],    m1 = sRm[c0 + 1];
        float q0 = sBb[c0],    q1 = sBb[c0 + 1];
        #pragma unroll
        for (int mt = 0; mt < 2; mt++) {
            acc[mt][nt][0] = (acc[mt][nt][0] - m0) * s0 + q0;
            acc[mt][nt][1] = (acc[mt][nt][1] - m1) * s1 + q1;
            acc[mt][nt][2] = (acc[mt][nt][2] - m0) * s0 + q0;
            acc[mt][nt][3] = (acc[mt][nt][3] - m1) * s1 + q1;
        }
    }

    // ---- softmax: 2-pass smem reduction across N-warps ----
    float* sPM = (float*)(smem + L_PM);
    float* sPS = (float*)(smem + L_PS);
    float* sOut = (float*)smem;                  // [128][66] floats

    #pragma unroll
    for (int h = 0; h < 4; h++) {
        int mt = h >> 1, hh = h & 1;
        float mx = -3.4e38f;
        #pragma unroll
        for (int nt = 0; nt < 5; nt++)
            mx = fmaxf(mx, fmaxf(acc[mt][nt][hh * 2], acc[mt][nt][hh * 2 + 1]));
        mx = fmaxf(mx, __shfl_xor_sync(0xffffffffu, mx, 1));
        mx = fmaxf(mx, __shfl_xor_sync(0xffffffffu, mx, 2));
        int row = wm * 32 + mt * 16 + hh * 8 + (lane >> 2);
        if ((lane & 3) == 0) sPM[row * 2 + wn] = mx;
    }
    __syncthreads();
    #pragma unroll
    for (int h = 0; h < 4; h++) {
        int mt = h >> 1, hh = h & 1;
        int row = wm * 32 + mt * 16 + hh * 8 + (lane >> 2);
        float m = fmaxf(sPM[row * 2], sPM[row * 2 + 1]);
        float sum = 0.f;
        #pragma unroll
        for (int nt = 0; nt < 5; nt++) {
            float e0 = __expf(acc[mt][nt][hh * 2] - m);
            float e1 = __expf(acc[mt][nt][hh * 2 + 1] - m);
            acc[mt][nt][hh * 2] = e0;
            acc[mt][nt][hh * 2 + 1] = e1;
            sum += e0 + e1;
        }
        sum += __shfl_xor_sync(0xffffffffu, sum, 1);
        sum += __shfl_xor_sync(0xffffffffu, sum, 2);
        if ((lane & 3) == 0) sPS[row * 2 + wn] = sum;
    }
    __syncthreads();
    const int ntmax = wn ? 3 : 5;
    #pragma unroll
    for (int h = 0; h < 4; h++) {
        int mt = h >> 1, hh = h & 1;
        int row = wm * 32 + mt * 16 + hh * 8 + (lane >> 2);
        float inv = 1.0f / (sPS[row * 2] + sPS[row * 2 + 1]);
        #pragma unroll
        for (int nt = 0; nt < 5; nt++) {
            if (nt < ntmax) {
                int col = wn * 40 + nt * 8 + (lane & 3) * 2;
                float2 v = make_float2(acc[mt][nt][hh * 2] * inv,
                                       acc[mt][nt][hh * 2 + 1] * inv);
                *(float2*)&sOut[row * 66 + col] = v;
            }
        }
    }
    __syncthreads();

    // ---- a_sum ----
    float* sAs = (float*)(smem + L_AS);
    {
        int k = tid & 63, qq = tid >> 6;
        float s = 0.f;
        #pragma unroll 8
        for (int r = qq * 32; r < qq * 32 + 32; r++) s += sOut[r * 66 + k];
        sAs[qq * 64 + k] = s;
    }
    __syncthreads();
    if (tid < KK)
        atomicAdd(&g_asum[b * KK + tid],
                  sAs[tid] + sAs[64 + tid] + sAs[128 + tid] + sAs[192 + tid]);

    // ---- assignment^T bf16 hi/lo, packed bf16x2 stores ----
    {
        int np = (tid & 63) * 2;
        int kh = (tid >> 6) * 16;
        uint32_t* aThi = (uint32_t*)(g_aThi + (size_t)b * KK * NN + n0 + np);
        uint32_t* aTlo = (uint32_t*)(g_aTlo + (size_t)b * KK * NN + n0 + np);
        #pragma unroll 4
        for (int kk2 = 0; kk2 < 16; kk2++) {
            int k = kh + kk2;
            float v0 = sOut[np * 66 + k];
            float v1 = sOut[(np + 1) * 66 + k];
            uint32_t hi, lo;
            split2(make_float2(v0, v1), hi, lo);
            aThi[(size_t)k * (NN / 2)] = hi;
            aTlo[(size_t)k * (NN / 2)] = lo;
        }
    }
}

// ---------------------------------------------------------------------------
// Kernel 2: vlad GEMM (mma.sync bf16x3): D[k_clu][d] = assign^T @ x
// CTA: 256 threads (2 M x 4 N warps), tile M=64 x N=128 d, FULL K(n)=2048
// in 64 stages. x: 2-buffer register prefetch. aT: 3-buffer cp.async,
// 2 stages in flight. Grid (4 dtiles, B).
// ---------------------------------------------------------------------------
// x buffers: 2 x 17408 (XH @0, XL @8704)   -> [0, 34816)
// aT buffers: 3 x 10240 (AH @0, AL @5120)  -> [34816, 65536)
#define VX_SZ 17408
#define VX_XL 8704
#define VA_BASE 34816
#define VA3_SZ 10240
#define VA_AL 5120
#define V_SMEM 65536

__global__ __launch_bounds__(256, 2) void k_vlad_mma(const float* __restrict__ x)
{
    extern __shared__ __align__(16) char sm[];
    const int tid = threadIdx.x, lane = tid & 31, w = tid >> 5;
    const int wm = w & 1, wn = w >> 1;
    const int b = blockIdx.y, d0 = blockIdx.x * 128;
    const float* xb = x + (size_t)b * NN * DD + d0;
    const __nv_bfloat16* aThi = g_aThi + (size_t)b * KK * NN;
    const __nv_bfloat16* aTlo = g_aTlo + (size_t)b * KK * NN;
    uint32_t sb32 = smem_to_u32(sm);

    float acc[2][4][4];
    #pragma unroll
    for (int mt = 0; mt < 2; mt++)
        #pragma unroll
        for (int nt = 0; nt < 4; nt++)
            #pragma unroll
            for (int e = 0; e < 4; e++) acc[mt][nt][e] = 0.f;

    const int xr_r = tid >> 5, xr_u = tid & 31;
    const int ar_r = tid >> 2, ar_u = tid & 3;

    auto cp_a = [&](int nc) {
        const int nbase = nc * 32;
        uint32_t base = sb32 + VA_BASE + (uint32_t)((nc % 3) * VA3_SZ);
        size_t ge = (size_t)ar_r * NN + nbase + ar_u * 8;
        CP_ASYNC16(base + ar_r * 80 + ar_u * 16, aThi + ge);
        CP_ASYNC16(base + VA_AL + ar_r * 80 + ar_u * 16, aTlo + ge);
        CP_COMMIT();
    };

    float4 xr[4];
    cp_a(0);
    cp_a(1);
    #pragma unroll
    for (int j = 0; j < 4; j++)
        xr[j] = *(const float4*)&xb[(size_t)(xr_r + j * 8) * DD + xr_u * 4];

    for (int nc = 0; nc < 64; nc++) {
        char* buf = sm + (nc & 1) * VX_SZ;
        #pragma unroll
        for (int j = 0; j < 4; j++) {
            uint32_t h0, l0, h1, l1;
            split2(make_float2(xr[j].x, xr[j].y), h0, l0);
            split2(make_float2(xr[j].z, xr[j].w), h1, l1);
            int off = (xr_r + j * 8) * 272 + xr_u * 8;
            *(uint2*)(buf + off) = make_uint2(h0, h1);
            *(uint2*)(buf + VX_XL + off) = make_uint2(l0, l1);
        }
        if (nc < 63) {
            const int nbase = (nc + 1) * 32;
            #pragma unroll
            for (int j = 0; j < 4; j++)
                xr[j] = *(const float4*)&xb[(size_t)(nbase + xr_r + j * 8) * DD + xr_u * 4];
        }
        if (nc < 63) CP_WAIT1(); else CP_WAIT0();
        __syncthreads();
        if (nc + 2 < 64) cp_a(nc + 2);

        uint32_t xbase = sb32 + (uint32_t)((nc & 1) * VX_SZ);
        uint32_t abase = sb32 + VA_BASE + (uint32_t)((nc % 3) * VA3_SZ);
        #pragma unroll
        for (int kt = 0; kt < 2; kt++) {
            uint32_t ah[2][4], al[2][4];
            #pragma unroll
            for (int mt = 0; mt < 2; mt++) {
                uint32_t aoff = (uint32_t)((wm * 32 + mt * 16 + (lane & 15)) * 80 +
                                           (kt * 16 + (lane >> 4) * 8) * 2);
                ldsm_x4(ah[mt], abase + aoff);
                ldsm_x4(al[mt], abase + VA_AL + aoff);
            }
            uint32_t bh[4][2], bl[4][2];
            #pragma unroll
            for (int p = 0; p < 2; p++) {
                uint32_t t[4];
                uint32_t boff = (uint32_t)((kt * 16 + (lane & 15)) * 272 +
                                           (wn * 32 + p * 16 + (lane >> 4) * 8) * 2);
                ldsm_x4t(t, xbase + boff);
                bh[2*p][0] = t[0]; bh[2*p][1] = t[1];
                bh[2*p+1][0] = t[2]; bh[2*p+1][1] = t[3];
                ldsm_x4t(t, xbase + VX_XL + boff);
                bl[2*p][0] = t[0]; bl[2*p][1] = t[1];
                bl[2*p+1][0] = t[2]; bl[2*p+1][1] = t[3];
            }
            #pragma unroll
            for (int nt = 0; nt < 4; nt++)
                #pragma unroll
                for (int mt = 0; mt < 2; mt++) {
                    mma_bf16(acc[mt][nt], ah[mt], bh[nt]);
                    mma_bf16(acc[mt][nt], ah[mt], bl[nt]);
                    mma_bf16(acc[mt][nt], al[mt], bh[nt]);
                }
        }
    }

    float* vp = g_vpart + (size_t)b * KK * DD;
    #pragma unroll
    for (int mt = 0; mt < 2; mt++) {
        int k0 = wm * 32 + mt * 16 + (lane >> 2);
        #pragma unroll
        for (int nt = 0; nt < 4; nt++) {
            int d = d0 + wn * 32 + nt * 8 + (lane & 3) * 2;
            *(float2*)&vp[(size_t)k0 * DD + d]       = make_float2(acc[mt][nt][0], acc[mt][nt][1]);
            *(float2*)&vp[(size_t)(k0 + 8) * DD + d] = make_float2(acc[mt][nt][2], acc[mt][nt][3]);
        }
    }
}

// ---------------------------------------------------------------------------
// Kernel 3: finisher — subtract a_sum*clusters2, transpose to out[b][d][k],
// per-(b,k) norm^2.
// ---------------------------------------------------------------------------
__global__ __launch_bounds__(256) void k_fin(float* __restrict__ out)
{
    __shared__ float sT[64][66];
    __shared__ float sN[64];
    const int b = blockIdx.y, dg = blockIdx.x;
    const int lane = threadIdx.x & 31, w = threadIdx.x >> 5;
    const float* vp = g_vpart + (size_t)b * KK * DD;

    #pragma unroll
    for (int kr = 0; kr < 8; kr++) {
        int k = w * 8 + kr;
        float as = g_asum[b * KK + k];
        int d = dg * 64 + lane;
        float v0 = vp[(size_t)k * DD + d]      - as * g_c2T[k * DD + d];
        float v1 = vp[(size_t)k * DD + d + 32] - as * g_c2T[k * DD + d + 32];
        sT[lane][k]      = v0;
        sT[lane + 32][k] = v1;
        float n2 = v0 * v0 + v1 * v1;
        #pragma unroll
        for (int o = 16; o >= 1; o >>= 1) n2 += __shfl_xor_sync(0xffffffffu, n2, o);
        if (lane == 0) sN[k] = n2;
    }
    __syncthreads();
    if (threadIdx.x < KK)
        atomicAdd(&g_norm2[b * KK + threadIdx.x], sN[threadIdx.x]);
    #pragma unroll
    for (int j = 0; j < 16; j++) {
        int idx = threadIdx.x + j * 256;
        int d = idx >> 6, k = idx & 63;
        out[((size_t)b * DD + dg * 64 + d) * KK + k] = sT[d][k];
    }
}

// ---------------------------------------------------------------------------
// Kernel 4: fused scale compute + in-place output scaling
// ---------------------------------------------------------------------------
__global__ __launch_bounds__(256) void k_out(float* __restrict__ out) {
    __shared__ float sInv[KK];
    __shared__ float sh[2];
    const int b = blockIdx.y, dg = blockIdx.x;
    const int t = threadIdx.x;
    if (t < KK) {
        float n2 = g_norm2[b * KK + t];
        float inv = 1.0f / fmaxf(sqrtf(n2), 1e-12f);
        float c = n2 * inv * inv;
        #pragma unroll
        for (int o = 16; o >= 1; o >>= 1) c += __shfl_xor_sync(0xffffffffu, c, o);
        if ((t & 31) == 0) sh[t >> 5] = c;
        sInv[t] = inv;
    }
    __syncthreads();
    float invt = 1.0f / fmaxf(sqrtf(sh[0] + sh[1]), 1e-12f);
    size_t base = (size_t)b * DD * KK + (size_t)dg * 4096;
    #pragma unroll
    for (int j = 0; j < 16; j++) {
        int i = t + j * 256;
        out[base + i] = out[base + i] * (sInv[i & 63] * invt);
    }
}

// ---------------------------------------------------------------------------
extern "C" void kernel_launch(void* const* d_in, const int* in_sizes, int n_in,
                              void* d_out, int out_size) {
    const float* x         = (const float*)d_in[0];
    const float* clusters  = (const float*)d_in[1];
    const float* clusters2 = (const float*)d_in[2];
    const float* bnw       = (const float*)d_in[3];
    const float* bnb       = (const float*)d_in[4];
    const float* rm        = (const float*)d_in[5];
    const float* rv        = (const float*)d_in[6];
    float* out = (float*)d_out;

    cudaFuncSetAttribute(k_logits_mma, cudaFuncAttributeMaxDynamicSharedMemorySize, L_SMEM);
    cudaFuncSetAttribute(k_vlad_mma, cudaFuncAttributeMaxDynamicSharedMemorySize, V_SMEM);

    k_prep<<<(DD * KGC + 255) / 256, 256>>>(clusters);
    k_prep2<<<KK, DD>>>(clusters2);
    dim3 g1(NN / 128, BB);
    k_logits_mma<<<g1, 256, L_SMEM>>>(x, bnw, bnb, rm, rv);
    dim3 g2(DD / 128, BB);
    k_vlad_mma<<<g2, 256, V_SMEM>>>(x);
    dim3 g3(8, BB);
    k_fin<<<g3, 256>>>(out);
    dim3 g4(8, BB);
    k_out<<<g4, 256>>>(out);
}

// round 15
// speedup vs baseline: 1.0478x; 1.0478x over previous
#include <cuda_runtime.h>
#include <cuda_bf16.h>
#include <cstdint>

#define BB 64
#define NN 2048
#define DD 512
#define KK 64
#define KGC 80

// Scratch (device globals — no allocation allowed)
__device__ __align__(16) __nv_bfloat16 g_aThi[(size_t)BB * KK * NN]; // assignT hi [b][k][n]
__device__ __align__(16) __nv_bfloat16 g_aTlo[(size_t)BB * KK * NN]; // assignT lo
__device__ float g_asum[BB * KK];
__device__ float g_norm2[BB * KK];
__device__ __align__(16) __nv_bfloat16 g_cHi[DD * KGC];
__device__ __align__(16) __nv_bfloat16 g_cLo[DD * KGC];
__device__ float g_c2T[KK * DD];

// ===================== helpers =====================
__device__ __forceinline__ uint32_t smem_to_u32(const void* p) {
    uint32_t a;
    asm("{ .reg .u64 t; cvta.to.shared.u64 t, %1; cvt.u32.u64 %0, t; }" : "=r"(a) : "l"(p));
    return a;
}
__device__ __forceinline__ void mma_bf16(float* c, const uint32_t* a, const uint32_t* b) {
    asm volatile("mma.sync.aligned.m16n8k16.row.col.f32.bf16.bf16.f32 "
        "{%0,%1,%2,%3}, {%4,%5,%6,%7}, {%8,%9}, {%0,%1,%2,%3};"
        : "+f"(c[0]), "+f"(c[1]), "+f"(c[2]), "+f"(c[3])
        : "r"(a[0]), "r"(a[1]), "r"(a[2]), "r"(a[3]), "r"(b[0]), "r"(b[1]));
}
__device__ __forceinline__ void ldsm_x4(uint32_t* r, uint32_t addr) {
    asm volatile("ldmatrix.sync.aligned.m8n8.x4.shared.b16 {%0,%1,%2,%3}, [%4];"
        : "=r"(r[0]), "=r"(r[1]), "=r"(r[2]), "=r"(r[3]) : "r"(addr));
}
__device__ __forceinline__ void ldsm_x4t(uint32_t* r, uint32_t addr) {
    asm volatile("ldmatrix.sync.aligned.m8n8.x4.trans.shared.b16 {%0,%1,%2,%3}, [%4];"
        : "=r"(r[0]), "=r"(r[1]), "=r"(r[2]), "=r"(r[3]) : "r"(addr));
}
__device__ __forceinline__ void ldsm_x2t(uint32_t* r, uint32_t addr) {
    asm volatile("ldmatrix.sync.aligned.m8n8.x2.trans.shared.b16 {%0,%1}, [%2];"
        : "=r"(r[0]), "=r"(r[1]) : "r"(addr));
}
__device__ __forceinline__ void split2(float2 v, uint32_t& hi, uint32_t& lo) {
    __nv_bfloat162 h = __float22bfloat162_rn(v);
    float2 hf = __bfloat1622float2(h);
    __nv_bfloat162 l = __float22bfloat162_rn(make_float2(v.x - hf.x, v.y - hf.y));
    hi = *(uint32_t*)&h;
    lo = *(uint32_t*)&l;
}
#define CP_ASYNC16(dst, src) \
    asm volatile("cp.async.cg.shared.global [%0], [%1], 16;" :: "r"(dst), "l"(src) : "memory")
#define CP_COMMIT() asm volatile("cp.async.commit_group;" ::: "memory")
#define CP_WAIT0()  asm volatile("cp.async.wait_group 0;" ::: "memory")

// ---------------------------------------------------------------------------
// Kernel P1: split clusters to bf16 hi/lo + zero accumulators
// ---------------------------------------------------------------------------
__global__ void k_prep(const float* __restrict__ clusters) {
    int i = blockIdx.x * 256 + threadIdx.x;
    if (i < DD * KGC) {
        float v = clusters[i];
        __nv_bfloat16 h = __float2bfloat16(v);
        g_cHi[i] = h;
        g_cLo[i] = __float2bfloat16(v - __bfloat162float(h));
    }
    if (i < BB * KK) { g_asum[i] = 0.0f; g_norm2[i] = 0.0f; }
}
// Kernel P2: transpose clusters2 [512][64] -> [64][512]
__global__ void k_prep2(const float* __restrict__ clusters2) {
    int k = blockIdx.x;
    int d = threadIdx.x;
    g_c2T[k * DD + d] = clusters2[d * KK + k];
}

// ---------------------------------------------------------------------------
// Kernel 1: logits GEMM (mma.sync bf16x3) + BN + softmax + a_sum + assignT
// CTA: 256 threads = 8 warps, 4 M-split x 2 N-split. Tile M=128 x N=80,
// K=512 in 16 chunks of 32 d, double-buffered smem, 1 sync/stage.
// A: register prefetch + convert + STS. B: cp.async.cg (bf16 pre-split).
// ---------------------------------------------------------------------------
#define LB_AH 0
#define LB_AL 10240
#define LB_BH 20480
#define LB_BL 26112
#define LB_SZ 31744
#define L_BN  63488      // 240 floats
#define L_AS  64448      // 256 floats
#define L_PM  65472      // 256 floats
#define L_PS  66496      // 256 floats
#define L_SMEM 67520

__global__ __launch_bounds__(256, 2) void k_logits_mma(
    const float* __restrict__ x,
    const float* __restrict__ bnw, const float* __restrict__ bnb,
    const float* __restrict__ rm, const float* __restrict__ rv)
{
    extern __shared__ __align__(16) char smem[];
    const int tid = threadIdx.x;
    const int lane = tid & 31, w = tid >> 5;
    const int wm = w & 3, wn = w >> 2;           // 4 M-warps x 2 N-warps
    const int b = blockIdx.y, n0 = blockIdx.x * 128;
    const float* xb = x + ((size_t)b * NN + n0) * DD;
    uint32_t sb32 = smem_to_u32(smem);

    float* sScale = (float*)(smem + L_BN);
    float* sRm = sScale + 80;
    float* sBb = sScale + 160;
    if (tid < KGC) {
        sScale[tid] = bnw[tid] * rsqrtf(rv[tid] + 1e-5f);
        sRm[tid] = rm[tid];
        sBb[tid] = bnb[tid];
    }

    float acc[2][5][4];
    #pragma unroll
    for (int mt = 0; mt < 2; mt++)
        #pragma unroll
        for (int nt = 0; nt < 5; nt++)
            #pragma unroll
            for (int e = 0; e < 4; e++) acc[mt][nt][e] = 0.f;

    const int xr_r = tid >> 3, xr_u = tid & 7;
    const int br0 = tid / 10, bc0 = tid - br0 * 10;
    const int bidx1 = tid + 256;
    const int u1 = bidx1 >= 320 ? bidx1 - 320 : bidx1;
    const int barr1 = bidx1 >= 320;
    const int br1 = u1 / 10, bc1 = u1 - br1 * 10;
    const int u2 = tid + 512 - 320;
    const int br2 = u2 / 10, bc2 = u2 - br2 * 10;
    const bool bp2 = tid < 128;

    auto cp_b = [&](int stage) {
        uint32_t base = sb32 + (uint32_t)((stage & 1) * LB_SZ);
        const __nv_bfloat16* s0 = g_cHi + (size_t)(stage * 32 + br0) * KGC + bc0 * 8;
        CP_ASYNC16(base + LB_BH + br0 * 176 + bc0 * 16, s0);
        const __nv_bfloat16* s1 = (barr1 ? g_cLo : g_cHi) + (size_t)(stage * 32 + br1) * KGC + bc1 * 8;
        CP_ASYNC16(base + (barr1 ? LB_BL : LB_BH) + br1 * 176 + bc1 * 16, s1);
        if (bp2) {
            const __nv_bfloat16* s2 = g_cLo + (size_t)(stage * 32 + br2) * KGC + bc2 * 8;
            CP_ASYNC16(base + LB_BL + br2 * 176 + bc2 * 16, s2);
        }
        CP_COMMIT();
    };

    float4 xr[4];
    cp_b(0);
    #pragma unroll
    for (int j = 0; j < 4; j++)
        xr[j] = *(const float4*)&xb[(size_t)(xr_r + j * 32) * DD + xr_u * 4];

    for (int dt = 0; dt < 16; dt++) {
        char* buf = smem + (dt & 1) * LB_SZ;
        #pragma unroll
        for (int j = 0; j < 4; j++) {
            uint32_t h0, l0, h1, l1;
            split2(make_float2(xr[j].x, xr[j].y), h0, l0);
            split2(make_float2(xr[j].z, xr[j].w), h1, l1);
            int off = (xr_r + j * 32) * 80 + xr_u * 8;
            *(uint2*)(buf + LB_AH + off) = make_uint2(h0, h1);
            *(uint2*)(buf + LB_AL + off) = make_uint2(l0, l1);
        }
        if (dt < 15) {
            #pragma unroll
            for (int j = 0; j < 4; j++)
                xr[j] = *(const float4*)&xb[(size_t)(xr_r + j * 32) * DD +
                                            (dt + 1) * 32 + xr_u * 4];
        }
        CP_WAIT0();
        __syncthreads();
        if (dt < 15) cp_b(dt + 1);

        uint32_t bufo = sb32 + (uint32_t)((dt & 1) * LB_SZ);
        #pragma unroll
        for (int kt = 0; kt < 2; kt++) {
            uint32_t ah[2][4], al[2][4];
            #pragma unroll
            for (int mt = 0; mt < 2; mt++) {
                uint32_t aoff = (uint32_t)((wm * 32 + mt * 16 + (lane & 15)) * 80 +
                                           (kt * 16 + (lane >> 4) * 8) * 2);
                ldsm_x4(ah[mt], bufo + LB_AH + aoff);
                ldsm_x4(al[mt], bufo + LB_AL + aoff);
            }
            uint32_t bh[5][2], bl[5][2];
            #pragma unroll
            for (int p = 0; p < 2; p++) {
                uint32_t t[4];
                uint32_t boff = (uint32_t)((kt * 16 + (lane & 15)) * 176 +
                                           (wn * 40 + p * 16 + (lane >> 4) * 8) * 2);
                ldsm_x4t(t, bufo + LB_BH + boff);
                bh[2*p][0] = t[0]; bh[2*p][1] = t[1];
                bh[2*p+1][0] = t[2]; bh[2*p+1][1] = t[3];
                ldsm_x4t(t, bufo + LB_BL + boff);
                bl[2*p][0] = t[0]; bl[2*p][1] = t[1];
                bl[2*p+1][0] = t[2]; bl[2*p+1][1] = t[3];
            }
            {
                uint32_t boff = (uint32_t)((kt * 16 + (lane & 15)) * 176 + (wn * 40 + 32) * 2);
                ldsm_x2t(bh[4], bufo + LB_BH + boff);
                ldsm_x2t(bl[4], bufo + LB_BL + boff);
            }
            #pragma unroll
            for (int nt = 0; nt < 5; nt++)
                #pragma unroll
                for (int mt = 0; mt < 2; mt++) {
                    mma_bf16(acc[mt][nt], ah[mt], bh[nt]);
                    mma_bf16(acc[mt][nt], ah[mt], bl[nt]);
                    mma_bf16(acc[mt][nt], al[mt], bh[nt]);
                }
        }
    }
    __syncthreads();

    // ---- BN affine ----
    #pragma unroll
    for (int nt = 0; nt < 5; nt++) {
        int c0 = wn * 40 + nt * 8 + (lane & 3) * 2;
        float s0 = sScale[c0], s1 = sScale[c0 + 1];
        float m0 = sRm[c0],    m1 = sRm[c0 + 1];
        float q0 = sBb[c0],    q1 = sBb[c0 + 1];
        #pragma unroll
        for (int mt = 0; mt < 2; mt++) {
            acc[mt][nt][0] = (acc[mt][nt][0] - m0) * s0 + q0;
            acc[mt][nt][1] = (acc[mt][nt][1] - m1) * s1 + q1;
            acc[mt][nt][2] = (acc[mt][nt][2] - m0) * s0 + q0;
            acc[mt][nt][3] = (acc[mt][nt][3] - m1) * s1 + q1;
        }
    }

    // ---- softmax: 2-pass smem reduction across N-warps ----
    float* sPM = (float*)(smem + L_PM);
    float* sPS = (float*)(smem + L_PS);
    float* sOut = (float*)smem;                  // [128][66] floats

    #pragma unroll
    for (int h = 0; h < 4; h++) {
        int mt = h >> 1, hh = h & 1;
        float mx = -3.4e38f;
        #pragma unroll
        for (int nt = 0; nt < 5; nt++)
            mx = fmaxf(mx, fmaxf(acc[mt][nt][hh * 2], acc[mt][nt][hh * 2 + 1]));
        mx = fmaxf(mx, __shfl_xor_sync(0xffffffffu, mx, 1));
        mx = fmaxf(mx, __shfl_xor_sync(0xffffffffu, mx, 2));
        int row = wm * 32 + mt * 16 + hh * 8 + (lane >> 2);
        if ((lane & 3) == 0) sPM[row * 2 + wn] = mx;
    }
    __syncthreads();
    #pragma unroll
    for (int h = 0; h < 4; h++) {
        int mt = h >> 1, hh = h & 1;
        int row = wm * 32 + mt * 16 + hh * 8 + (lane >> 2);
        float m = fmaxf(sPM[row * 2], sPM[row * 2 + 1]);
        float sum = 0.f;
        #pragma unroll
        for (int nt = 0; nt < 5; nt++) {
            float e0 = __expf(acc[mt][nt][hh * 2] - m);
            float e1 = __expf(acc[mt][nt][hh * 2 + 1] - m);
            acc[mt][nt][hh * 2] = e0;
            acc[mt][nt][hh * 2 + 1] = e1;
            sum += e0 + e1;
        }
        sum += __shfl_xor_sync(0xffffffffu, sum, 1);
        sum += __shfl_xor_sync(0xffffffffu, sum, 2);
        if ((lane & 3) == 0) sPS[row * 2 + wn] = sum;
    }
    __syncthreads();
    const int ntmax = wn ? 3 : 5;
    #pragma unroll
    for (int h = 0; h < 4; h++) {
        int mt = h >> 1, hh = h & 1;
        int row = wm * 32 + mt * 16 + hh * 8 + (lane >> 2);
        float inv = 1.0f / (sPS[row * 2] + sPS[row * 2 + 1]);
        #pragma unroll
        for (int nt = 0; nt < 5; nt++) {
            if (nt < ntmax) {
                int col = wn * 40 + nt * 8 + (lane & 3) * 2;
                float2 v = make_float2(acc[mt][nt][hh * 2] * inv,
                                       acc[mt][nt][hh * 2 + 1] * inv);
                *(float2*)&sOut[row * 66 + col] = v;
            }
        }
    }
    __syncthreads();

    // ---- a_sum ----
    float* sAs = (float*)(smem + L_AS);
    {
        int k = tid & 63, qq = tid >> 6;
        float s = 0.f;
        #pragma unroll 8
        for (int r = qq * 32; r < qq * 32 + 32; r++) s += sOut[r * 66 + k];
        sAs[qq * 64 + k] = s;
    }
    __syncthreads();
    if (tid < KK)
        atomicAdd(&g_asum[b * KK + tid],
                  sAs[tid] + sAs[64 + tid] + sAs[128 + tid] + sAs[192 + tid]);

    // ---- assignment^T bf16 hi/lo, packed bf16x2 stores ----
    {
        int np = (tid & 63) * 2;
        int kh = (tid >> 6) * 16;
        uint32_t* aThi = (uint32_t*)(g_aThi + (size_t)b * KK * NN + n0 + np);
        uint32_t* aTlo = (uint32_t*)(g_aTlo + (size_t)b * KK * NN + n0 + np);
        #pragma unroll 4
        for (int kk2 = 0; kk2 < 16; kk2++) {
            int k = kh + kk2;
            float v0 = sOut[np * 66 + k];
            float v1 = sOut[(np + 1) * 66 + k];
            uint32_t hi, lo;
            split2(make_float2(v0, v1), hi, lo);
            aThi[(size_t)k * (NN / 2)] = hi;
            aTlo[(size_t)k * (NN / 2)] = lo;
        }
    }
}

// ---------------------------------------------------------------------------
// Kernel 2: vlad GEMM (mma.sync bf16x3) + FUSED finisher epilogue.
// D[k][d] = assignT @ x; then v = D - a_sum*c2T, norm2 atomics, transposed
// coalesced store straight into out[b][d][k]. Grid (4 dtiles, B).
// ---------------------------------------------------------------------------
#define VB_XH 0
#define VB_XL 8704
#define VB_AH 17408
#define VB_AL 22528
#define VB_SZ 27648

__global__ __launch_bounds__(256, 2) void k_vlad_mma(const float* __restrict__ x,
                                                     float* __restrict__ out)
{
    __shared__ __align__(16) char sm[2 * VB_SZ];
    const int tid = threadIdx.x, lane = tid & 31, w = tid >> 5;
    const int wm = w & 1, wn = w >> 1;
    const int b = blockIdx.y, d0 = blockIdx.x * 128;
    const float* xb = x + (size_t)b * NN * DD + d0;
    const __nv_bfloat16* aThi = g_aThi + (size_t)b * KK * NN;
    const __nv_bfloat16* aTlo = g_aTlo + (size_t)b * KK * NN;
    uint32_t sb32 = smem_to_u32(sm);

    float acc[2][4][4];
    #pragma unroll
    for (int mt = 0; mt < 2; mt++)
        #pragma unroll
        for (int nt = 0; nt < 4; nt++)
            #pragma unroll
            for (int e = 0; e < 4; e++) acc[mt][nt][e] = 0.f;

    const int xr_r = tid >> 5, xr_u = tid & 31;
    const int ar_r = tid >> 2, ar_u = tid & 3;

    auto cp_a = [&](int nc) {
        const int nbase = nc * 32;
        uint32_t base = sb32 + (uint32_t)((nc & 1) * VB_SZ);
        size_t ge = (size_t)ar_r * NN + nbase + ar_u * 8;
        CP_ASYNC16(base + VB_AH + ar_r * 80 + ar_u * 16, aThi + ge);
        CP_ASYNC16(base + VB_AL + ar_r * 80 + ar_u * 16, aTlo + ge);
        CP_COMMIT();
    };

    float4 xr[4];
    cp_a(0);
    #pragma unroll
    for (int j = 0; j < 4; j++)
        xr[j] = *(const float4*)&xb[(size_t)(xr_r + j * 8) * DD + xr_u * 4];

    for (int nc = 0; nc < 64; nc++) {
        char* buf = sm + (nc & 1) * VB_SZ;
        #pragma unroll
        for (int j = 0; j < 4; j++) {
            uint32_t h0, l0, h1, l1;
            split2(make_float2(xr[j].x, xr[j].y), h0, l0);
            split2(make_float2(xr[j].z, xr[j].w), h1, l1);
            int off = (xr_r + j * 8) * 272 + xr_u * 8;
            *(uint2*)(buf + VB_XH + off) = make_uint2(h0, h1);
            *(uint2*)(buf + VB_XL + off) = make_uint2(l0, l1);
        }
        if (nc < 63) {
            const int nbase = (nc + 1) * 32;
            #pragma unroll
            for (int j = 0; j < 4; j++)
                xr[j] = *(const float4*)&xb[(size_t)(nbase + xr_r + j * 8) * DD + xr_u * 4];
        }
        CP_WAIT0();
        __syncthreads();
        if (nc < 63) cp_a(nc + 1);

        uint32_t bufo = sb32 + (uint32_t)((nc & 1) * VB_SZ);
        #pragma unroll
        for (int kt = 0; kt < 2; kt++) {
            uint32_t ah[2][4], al[2][4];
            #pragma unroll
            for (int mt = 0; mt < 2; mt++) {
                uint32_t aoff = (uint32_t)((wm * 32 + mt * 16 + (lane & 15)) * 80 +
                                           (kt * 16 + (lane >> 4) * 8) * 2);
                ldsm_x4(ah[mt], bufo + VB_AH + aoff);
                ldsm_x4(al[mt], bufo + VB_AL + aoff);
            }
            uint32_t bh[4][2], bl[4][2];
            #pragma unroll
            for (int p = 0; p < 2; p++) {
                uint32_t t[4];
                uint32_t boff = (uint32_t)((kt * 16 + (lane & 15)) * 272 +
                                           (wn * 32 + p * 16 + (lane >> 4) * 8) * 2);
                ldsm_x4t(t, bufo + VB_XH + boff);
                bh[2*p][0] = t[0]; bh[2*p][1] = t[1];
                bh[2*p+1][0] = t[2]; bh[2*p+1][1] = t[3];
                ldsm_x4t(t, bufo + VB_XL + boff);
                bl[2*p][0] = t[0]; bl[2*p][1] = t[1];
                bl[2*p+1][0] = t[2]; bl[2*p+1][1] = t[3];
            }
            #pragma unroll
            for (int nt = 0; nt < 4; nt++)
                #pragma unroll
                for (int mt = 0; mt < 2; mt++) {
                    mma_bf16(acc[mt][nt], ah[mt], bh[nt]);
                    mma_bf16(acc[mt][nt], ah[mt], bl[nt]);
                    mma_bf16(acc[mt][nt], al[mt], bh[nt]);
                }
        }
    }

    // ===== fused finisher epilogue =====
    __syncthreads();                     // mainloop smem reads complete
    float* sT = (float*)sm;              // [128 d][68 k] floats = 34816 B

    #pragma unroll
    for (int mt = 0; mt < 2; mt++) {
        int k0 = wm * 32 + mt * 16 + (lane >> 2);
        float a0 = g_asum[b * KK + k0];
        float a8 = g_asum[b * KK + k0 + 8];
        float n20 = 0.f, n28 = 0.f;
        #pragma unroll
        for (int nt = 0; nt < 4; nt++) {
            int d = wn * 32 + nt * 8 + (lane & 3) * 2;
            const float* c2 = g_c2T + (size_t)k0 * DD + d0 + d;
            float2 c0 = *(const float2*)c2;
            float2 c8 = *(const float2*)(c2 + 8 * DD);
            float v00 = acc[mt][nt][0] - a0 * c0.x;
            float v01 = acc[mt][nt][1] - a0 * c0.y;
            float v80 = acc[mt][nt][2] - a8 * c8.x;
            float v81 = acc[mt][nt][3] - a8 * c8.y;
            sT[d * 68 + k0]           = v00;
            sT[(d + 1) * 68 + k0]     = v01;
            sT[d * 68 + k0 + 8]       = v80;
            sT[(d + 1) * 68 + k0 + 8] = v81;
            n20 += v00 * v00 + v01 * v01;
            n28 += v80 * v80 + v81 * v81;
        }
        n20 += __shfl_xor_sync(0xffffffffu, n20, 1);
        n20 += __shfl_xor_sync(0xffffffffu, n20, 2);
        n28 += __shfl_xor_sync(0xffffffffu, n28, 1);
        n28 += __shfl_xor_sync(0xffffffffu, n28, 2);
        if ((lane & 3) == 0) {
            atomicAdd(&g_norm2[b * KK + k0], n20);
            atomicAdd(&g_norm2[b * KK + k0 + 8], n28);
        }
    }
    __syncthreads();

    // coalesced write out[b][d0+d][k]
    float* ob = out + ((size_t)b * DD + d0) * KK;
    #pragma unroll
    for (int j = 0; j < 8; j++) {
        int idx = tid + j * 256;          // 0..2047 float4 units
        int d = idx >> 4, u = idx & 15;
        float4 v = make_float4(sT[d * 68 + u * 4],     sT[d * 68 + u * 4 + 1],
                               sT[d * 68 + u * 4 + 2], sT[d * 68 + u * 4 + 3]);
        *(float4*)&ob[(size_t)d * KK + u * 4] = v;
    }
}

// ---------------------------------------------------------------------------
// Kernel 3: fused scale compute + in-place output scaling
// ---------------------------------------------------------------------------
__global__ __launch_bounds__(256) void k_out(float* __restrict__ out) {
    __shared__ float sInv[KK];
    __shared__ float sh[2];
    const int b = blockIdx.y, dg = blockIdx.x;
    const int t = threadIdx.x;
    if (t < KK) {
        float n2 = g_norm2[b * KK + t];
        float inv = 1.0f / fmaxf(sqrtf(n2), 1e-12f);
        float c = n2 * inv * inv;
        #pragma unroll
        for (int o = 16; o >= 1; o >>= 1) c += __shfl_xor_sync(0xffffffffu, c, o);
        if ((t & 31) == 0) sh[t >> 5] = c;
        sInv[t] = inv;
    }
    __syncthreads();
    float invt = 1.0f / fmaxf(sqrtf(sh[0] + sh[1]), 1e-12f);
    size_t base = (size_t)b * DD * KK + (size_t)dg * 4096;
    #pragma unroll
    for (int j = 0; j < 16; j++) {
        int i = t + j * 256;
        out[base + i] = out[base + i] * (sInv[i & 63] * invt);
    }
}

// ---------------------------------------------------------------------------
extern "C" void kernel_launch(void* const* d_in, const int* in_sizes, int n_in,
                              void* d_out, int out_size) {
    const float* x         = (const float*)d_in[0];
    const float* clusters  = (const float*)d_in[1];
    const float* clusters2 = (const float*)d_in[2];
    const float* bnw       = (const float*)d_in[3];
    const float* bnb       = (const float*)d_in[4];
    const float* rm        = (const float*)d_in[5];
    const float* rv        = (const float*)d_in[6];
    float* out = (float*)d_out;

    cudaFuncSetAttribute(k_logits_mma, cudaFuncAttributeMaxDynamicSharedMemorySize, L_SMEM);

    k_prep<<<(DD * KGC + 255) / 256, 256>>>(clusters);
    k_prep2<<<KK, DD>>>(clusters2);
    dim3 g1(NN / 128, BB);
    k_logits_mma<<<g1, 256, L_SMEM>>>(x, bnw, bnb, rm, rv);
    dim3 g2(DD / 128, BB);
    k_vlad_mma<<<g2, 256>>>(x, out);
    dim3 g4(8, BB);
    k_out<<<g4, 256>>>(out);
}

// round 16
// speedup vs baseline: 1.0703x; 1.0215x over previous
#include <cuda_runtime.h>
#include <cuda_bf16.h>
#include <cstdint>

#define BB 64
#define NN 2048
#define DD 512
#define KK 64
#define KGC 80

// Scratch (device globals — no allocation allowed)
__device__ __align__(16) __nv_bfloat16 g_aThi[(size_t)BB * KK * NN]; // assignT hi [b][k][n]
__device__ __align__(16) __nv_bfloat16 g_aTlo[(size_t)BB * KK * NN]; // assignT lo
__device__ float g_asum[BB * KK];
__device__ float g_norm2[BB * KK];
__device__ __align__(16) __nv_bfloat16 g_cHi[DD * KGC];
__device__ __align__(16) __nv_bfloat16 g_cLo[DD * KGC];
__device__ float g_c2T[KK * DD];

// ===================== helpers =====================
__device__ __forceinline__ uint32_t smem_to_u32(const void* p) {
    uint32_t a;
    asm("{ .reg .u64 t; cvta.to.shared.u64 t, %1; cvt.u32.u64 %0, t; }" : "=r"(a) : "l"(p));
    return a;
}
__device__ __forceinline__ void mma_bf16(float* c, const uint32_t* a, const uint32_t* b) {
    asm volatile("mma.sync.aligned.m16n8k16.row.col.f32.bf16.bf16.f32 "
        "{%0,%1,%2,%3}, {%4,%5,%6,%7}, {%8,%9}, {%0,%1,%2,%3};"
        : "+f"(c[0]), "+f"(c[1]), "+f"(c[2]), "+f"(c[3])
        : "r"(a[0]), "r"(a[1]), "r"(a[2]), "r"(a[3]), "r"(b[0]), "r"(b[1]));
}
__device__ __forceinline__ void ldsm_x4(uint32_t* r, uint32_t addr) {
    asm volatile("ldmatrix.sync.aligned.m8n8.x4.shared.b16 {%0,%1,%2,%3}, [%4];"
        : "=r"(r[0]), "=r"(r[1]), "=r"(r[2]), "=r"(r[3]) : "r"(addr));
}
__device__ __forceinline__ void ldsm_x4t(uint32_t* r, uint32_t addr) {
    asm volatile("ldmatrix.sync.aligned.m8n8.x4.trans.shared.b16 {%0,%1,%2,%3}, [%4];"
        : "=r"(r[0]), "=r"(r[1]), "=r"(r[2]), "=r"(r[3]) : "r"(addr));
}
__device__ __forceinline__ void ldsm_x2t(uint32_t* r, uint32_t addr) {
    asm volatile("ldmatrix.sync.aligned.m8n8.x2.trans.shared.b16 {%0,%1}, [%2];"
        : "=r"(r[0]), "=r"(r[1]) : "r"(addr));
}
__device__ __forceinline__ void split2(float2 v, uint32_t& hi, uint32_t& lo) {
    __nv_bfloat162 h = __float22bfloat162_rn(v);
    float2 hf = __bfloat1622float2(h);
    __nv_bfloat162 l = __float22bfloat162_rn(make_float2(v.x - hf.x, v.y - hf.y));
    hi = *(uint32_t*)&h;
    lo = *(uint32_t*)&l;
}
#define CP_ASYNC16(dst, src) \
    asm volatile("cp.async.cg.shared.global [%0], [%1], 16;" :: "r"(dst), "l"(src) : "memory")
#define CP_COMMIT() asm volatile("cp.async.commit_group;" ::: "memory")
#define CP_WAIT0()  asm volatile("cp.async.wait_group 0;" ::: "memory")

// ---------------------------------------------------------------------------
// Kernel P: unified prep — cluster bf16 split + clusters2 transpose + zeroing
// ---------------------------------------------------------------------------
__global__ void k_prep(const float* __restrict__ clusters,
                       const float* __restrict__ clusters2) {
    int i = blockIdx.x * 256 + threadIdx.x;   // 0 .. 40959
    if (i < DD * KGC) {
        float v = clusters[i];
        __nv_bfloat16 h = __float2bfloat16(v);
        g_cHi[i] = h;
        g_cLo[i] = __float2bfloat16(v - __bfloat162float(h));
    }
    if (i < KK * DD) {
        int k = i >> 9, d = i & 511;
        g_c2T[i] = clusters2[d * KK + k];
    }
    if (i < BB * KK) { g_asum[i] = 0.0f; g_norm2[i] = 0.0f; }
}

// ---------------------------------------------------------------------------
// Kernel 1: logits GEMM (mma.sync bf16x3) + BN + softmax + a_sum + assignT
// CTA: 256 threads = 8 warps, 4 M-split x 2 N-split. Tile M=128 x N=80,
// K=512 in 16 chunks of 32 d, double-buffered smem, 1 sync/stage.
// A: register prefetch + convert + STS. B: cp.async.cg (bf16 pre-split).
// ---------------------------------------------------------------------------
#define LB_AH 0
#define LB_AL 10240
#define LB_BH 20480
#define LB_BL 26112
#define LB_SZ 31744
#define L_BN  63488      // 240 floats
#define L_AS  64448      // 256 floats
#define L_PM  65472      // 256 floats
#define L_PS  66496      // 256 floats
#define L_SMEM 67520

__global__ __launch_bounds__(256, 2) void k_logits_mma(
    const float* __restrict__ x,
    const float* __restrict__ bnw, const float* __restrict__ bnb,
    const float* __restrict__ rm, const float* __restrict__ rv)
{
    extern __shared__ __align__(16) char smem[];
    const int tid = threadIdx.x;
    const int lane = tid & 31, w = tid >> 5;
    const int wm = w & 3, wn = w >> 2;           // 4 M-warps x 2 N-warps
    const int b = blockIdx.y, n0 = blockIdx.x * 128;
    const float* xb = x + ((size_t)b * NN + n0) * DD;
    uint32_t sb32 = smem_to_u32(smem);

    float* sScale = (float*)(smem + L_BN);
    float* sRm = sScale + 80;
    float* sBb = sScale + 160;
    if (tid < KGC) {
        sScale[tid] = bnw[tid] * rsqrtf(rv[tid] + 1e-5f);
        sRm[tid] = rm[tid];
        sBb[tid] = bnb[tid];
    }

    float acc[2][5][4];
    #pragma unroll
    for (int mt = 0; mt < 2; mt++)
        #pragma unroll
        for (int nt = 0; nt < 5; nt++)
            #pragma unroll
            for (int e = 0; e < 4; e++) acc[mt][nt][e] = 0.f;

    const int xr_r = tid >> 3, xr_u = tid & 7;
    const int br0 = tid / 10, bc0 = tid - br0 * 10;
    const int bidx1 = tid + 256;
    const int u1 = bidx1 >= 320 ? bidx1 - 320 : bidx1;
    const int barr1 = bidx1 >= 320;
    const int br1 = u1 / 10, bc1 = u1 - br1 * 10;
    const int u2 = tid + 512 - 320;
    const int br2 = u2 / 10, bc2 = u2 - br2 * 10;
    const bool bp2 = tid < 128;

    auto cp_b = [&](int stage) {
        uint32_t base = sb32 + (uint32_t)((stage & 1) * LB_SZ);
        const __nv_bfloat16* s0 = g_cHi + (size_t)(stage * 32 + br0) * KGC + bc0 * 8;
        CP_ASYNC16(base + LB_BH + br0 * 176 + bc0 * 16, s0);
        const __nv_bfloat16* s1 = (barr1 ? g_cLo : g_cHi) + (size_t)(stage * 32 + br1) * KGC + bc1 * 8;
        CP_ASYNC16(base + (barr1 ? LB_BL : LB_BH) + br1 * 176 + bc1 * 16, s1);
        if (bp2) {
            const __nv_bfloat16* s2 = g_cLo + (size_t)(stage * 32 + br2) * KGC + bc2 * 8;
            CP_ASYNC16(base + LB_BL + br2 * 176 + bc2 * 16, s2);
        }
        CP_COMMIT();
    };

    float4 xr[4];
    cp_b(0);
    #pragma unroll
    for (int j = 0; j < 4; j++)
        xr[j] = *(const float4*)&xb[(size_t)(xr_r + j * 32) * DD + xr_u * 4];

    for (int dt = 0; dt < 16; dt++) {
        char* buf = smem + (dt & 1) * LB_SZ;
        #pragma unroll
        for (int j = 0; j < 4; j++) {
            uint32_t h0, l0, h1, l1;
            split2(make_float2(xr[j].x, xr[j].y), h0, l0);
            split2(make_float2(xr[j].z, xr[j].w), h1, l1);
            int off = (xr_r + j * 32) * 80 + xr_u * 8;
            *(uint2*)(buf + LB_AH + off) = make_uint2(h0, h1);
            *(uint2*)(buf + LB_AL + off) = make_uint2(l0, l1);
        }
        if (dt < 15) {
            #pragma unroll
            for (int j = 0; j < 4; j++)
                xr[j] = *(const float4*)&xb[(size_t)(xr_r + j * 32) * DD +
                                            (dt + 1) * 32 + xr_u * 4];
        }
        CP_WAIT0();
        __syncthreads();
        if (dt < 15) cp_b(dt + 1);

        uint32_t bufo = sb32 + (uint32_t)((dt & 1) * LB_SZ);
        #pragma unroll
        for (int kt = 0; kt < 2; kt++) {
            uint32_t ah[2][4], al[2][4];
            #pragma unroll
            for (int mt = 0; mt < 2; mt++) {
                uint32_t aoff = (uint32_t)((wm * 32 + mt * 16 + (lane & 15)) * 80 +
                                           (kt * 16 + (lane >> 4) * 8) * 2);
                ldsm_x4(ah[mt], bufo + LB_AH + aoff);
                ldsm_x4(al[mt], bufo + LB_AL + aoff);
            }
            uint32_t bh[5][2], bl[5][2];
            #pragma unroll
            for (int p = 0; p < 2; p++) {
                uint32_t t[4];
                uint32_t boff = (uint32_t)((kt * 16 + (lane & 15)) * 176 +
                                           (wn * 40 + p * 16 + (lane >> 4) * 8) * 2);
                ldsm_x4t(t, bufo + LB_BH + boff);
                bh[2*p][0] = t[0]; bh[2*p][1] = t[1];
                bh[2*p+1][0] = t[2]; bh[2*p+1][1] = t[3];
                ldsm_x4t(t, bufo + LB_BL + boff);
                bl[2*p][0] = t[0]; bl[2*p][1] = t[1];
                bl[2*p+1][0] = t[2]; bl[2*p+1][1] = t[3];
            }
            {
                uint32_t boff = (uint32_t)((kt * 16 + (lane & 15)) * 176 + (wn * 40 + 32) * 2);
                ldsm_x2t(bh[4], bufo + LB_BH + boff);
                ldsm_x2t(bl[4], bufo + LB_BL + boff);
            }
            #pragma unroll
            for (int nt = 0; nt < 5; nt++)
                #pragma unroll
                for (int mt = 0; mt < 2; mt++) {
                    mma_bf16(acc[mt][nt], ah[mt], bh[nt]);
                    mma_bf16(acc[mt][nt], ah[mt], bl[nt]);
                    mma_bf16(acc[mt][nt], al[mt], bh[nt]);
                }
        }
    }
    __syncthreads();

    // ---- BN affine ----
    #pragma unroll
    for (int nt = 0; nt < 5; nt++) {
        int c0 = wn * 40 + nt * 8 + (lane & 3) * 2;
        float s0 = sScale[c0], s1 = sScale[c0 + 1];
        float m0 = sRm[c0],    m1 = sRm[c0 + 1];
        float q0 = sBb[c0],    q1 = sBb[c0 + 1];
        #pragma unroll
        for (int mt = 0; mt < 2; mt++) {
            acc[mt][nt][0] = (acc[mt][nt][0] - m0) * s0 + q0;
            acc[mt][nt][1] = (acc[mt][nt][1] - m1) * s1 + q1;
            acc[mt][nt][2] = (acc[mt][nt][2] - m0) * s0 + q0;
            acc[mt][nt][3] = (acc[mt][nt][3] - m1) * s1 + q1;
        }
    }

    // ---- softmax: 2-pass smem reduction across N-warps ----
    float* sPM = (float*)(smem + L_PM);
    float* sPS = (float*)(smem + L_PS);
    float* sOut = (float*)smem;                  // [128][66] floats

    #pragma unroll
    for (int h = 0; h < 4; h++) {
        int mt = h >> 1, hh = h & 1;
        float mx = -3.4e38f;
        #pragma unroll
        for (int nt = 0; nt < 5; nt++)
            mx = fmaxf(mx, fmaxf(acc[mt][nt][hh * 2], acc[mt][nt][hh * 2 + 1]));
        mx = fmaxf(mx, __shfl_xor_sync(0xffffffffu, mx, 1));
        mx = fmaxf(mx, __shfl_xor_sync(0xffffffffu, mx, 2));
        int row = wm * 32 + mt * 16 + hh * 8 + (lane >> 2);
        if ((lane & 3) == 0) sPM[row * 2 + wn] = mx;
    }
    __syncthreads();
    #pragma unroll
    for (int h = 0; h < 4; h++) {
        int mt = h >> 1, hh = h & 1;
        int row = wm * 32 + mt * 16 + hh * 8 + (lane >> 2);
        float m = fmaxf(sPM[row * 2], sPM[row * 2 + 1]);
        float sum = 0.f;
        #pragma unroll
        for (int nt = 0; nt < 5; nt++) {
            float e0 = __expf(acc[mt][nt][hh * 2] - m);
            float e1 = __expf(acc[mt][nt][hh * 2 + 1] - m);
            acc[mt][nt][hh * 2] = e0;
            acc[mt][nt][hh * 2 + 1] = e1;
            sum += e0 + e1;
        }
        sum += __shfl_xor_sync(0xffffffffu, sum, 1);
        sum += __shfl_xor_sync(0xffffffffu, sum, 2);
        if ((lane & 3) == 0) sPS[row * 2 + wn] = sum;
    }
    __syncthreads();
    const int ntmax = wn ? 3 : 5;
    #pragma unroll
    for (int h = 0; h < 4; h++) {
        int mt = h >> 1, hh = h & 1;
        int row = wm * 32 + mt * 16 + hh * 8 + (lane >> 2);
        float inv = 1.0f / (sPS[row * 2] + sPS[row * 2 + 1]);
        #pragma unroll
        for (int nt = 0; nt < 5; nt++) {
            if (nt < ntmax) {
                int col = wn * 40 + nt * 8 + (lane & 3) * 2;
                float2 v = make_float2(acc[mt][nt][hh * 2] * inv,
                                       acc[mt][nt][hh * 2 + 1] * inv);
                *(float2*)&sOut[row * 66 + col] = v;
            }
        }
    }
    __syncthreads();

    // ---- a_sum ----
    float* sAs = (float*)(smem + L_AS);
    {
        int k = tid & 63, qq = tid >> 6;
        float s = 0.f;
        #pragma unroll 8
        for (int r = qq * 32; r < qq * 32 + 32; r++) s += sOut[r * 66 + k];
        sAs[qq * 64 + k] = s;
    }
    __syncthreads();
    if (tid < KK)
        atomicAdd(&g_asum[b * KK + tid],
                  sAs[tid] + sAs[64 + tid] + sAs[128 + tid] + sAs[192 + tid]);

    // ---- assignment^T bf16 hi/lo, packed bf16x2 stores ----
    {
        int np = (tid & 63) * 2;
        int kh = (tid >> 6) * 16;
        uint32_t* aThi = (uint32_t*)(g_aThi + (size_t)b * KK * NN + n0 + np);
        uint32_t* aTlo = (uint32_t*)(g_aTlo + (size_t)b * KK * NN + n0 + np);
        #pragma unroll 4
        for (int kk2 = 0; kk2 < 16; kk2++) {
            int k = kh + kk2;
            float v0 = sOut[np * 66 + k];
            float v1 = sOut[(np + 1) * 66 + k];
            uint32_t hi, lo;
            split2(make_float2(v0, v1), hi, lo);
            aThi[(size_t)k * (NN / 2)] = hi;
            aTlo[(size_t)k * (NN / 2)] = lo;
        }
    }
}

// ---------------------------------------------------------------------------
// Kernel 2: vlad GEMM (mma.sync bf16x3) + FUSED finisher epilogue.
// D[k][d] = assignT @ x; then v = D - a_sum*c2T, norm2 atomics, transposed
// coalesced store straight into out[b][d][k]. Grid (4 dtiles, B).
// ---------------------------------------------------------------------------
#define VB_XH 0
#define VB_XL 8704
#define VB_AH 17408
#define VB_AL 22528
#define VB_SZ 27648

__global__ __launch_bounds__(256, 2) void k_vlad_mma(const float* __restrict__ x,
                                                     float* __restrict__ out)
{
    __shared__ __align__(16) char sm[2 * VB_SZ];
    const int tid = threadIdx.x, lane = tid & 31, w = tid >> 5;
    const int wm = w & 1, wn = w >> 1;
    const int b = blockIdx.y, d0 = blockIdx.x * 128;
    const float* xb = x + (size_t)b * NN * DD + d0;
    const __nv_bfloat16* aThi = g_aThi + (size_t)b * KK * NN;
    const __nv_bfloat16* aTlo = g_aTlo + (size_t)b * KK * NN;
    uint32_t sb32 = smem_to_u32(sm);

    float acc[2][4][4];
    #pragma unroll
    for (int mt = 0; mt < 2; mt++)
        #pragma unroll
        for (int nt = 0; nt < 4; nt++)
            #pragma unroll
            for (int e = 0; e < 4; e++) acc[mt][nt][e] = 0.f;

    const int xr_r = tid >> 5, xr_u = tid & 31;
    const int ar_r = tid >> 2, ar_u = tid & 3;

    auto cp_a = [&](int nc) {
        const int nbase = nc * 32;
        uint32_t base = sb32 + (uint32_t)((nc & 1) * VB_SZ);
        size_t ge = (size_t)ar_r * NN + nbase + ar_u * 8;
        CP_ASYNC16(base + VB_AH + ar_r * 80 + ar_u * 16, aThi + ge);
        CP_ASYNC16(base + VB_AL + ar_r * 80 + ar_u * 16, aTlo + ge);
        CP_COMMIT();
    };

    float4 xr[4];
    cp_a(0);
    #pragma unroll
    for (int j = 0; j < 4; j++)
        xr[j] = *(const float4*)&xb[(size_t)(xr_r + j * 8) * DD + xr_u * 4];

    for (int nc = 0; nc < 64; nc++) {
        char* buf = sm + (nc & 1) * VB_SZ;
        #pragma unroll
        for (int j = 0; j < 4; j++) {
            uint32_t h0, l0, h1, l1;
            split2(make_float2(xr[j].x, xr[j].y), h0, l0);
            split2(make_float2(xr[j].z, xr[j].w), h1, l1);
            int off = (xr_r + j * 8) * 272 + xr_u * 8;
            *(uint2*)(buf + VB_XH + off) = make_uint2(h0, h1);
            *(uint2*)(buf + VB_XL + off) = make_uint2(l0, l1);
        }
        if (nc < 63) {
            const int nbase = (nc + 1) * 32;
            #pragma unroll
            for (int j = 0; j < 4; j++)
                xr[j] = *(const float4*)&xb[(size_t)(nbase + xr_r + j * 8) * DD + xr_u * 4];
        }
        CP_WAIT0();
        __syncthreads();
        if (nc < 63) cp_a(nc + 1);

        uint32_t bufo = sb32 + (uint32_t)((nc & 1) * VB_SZ);
        #pragma unroll
        for (int kt = 0; kt < 2; kt++) {
            uint32_t ah[2][4], al[2][4];
            #pragma unroll
            for (int mt = 0; mt < 2; mt++) {
                uint32_t aoff = (uint32_t)((wm * 32 + mt * 16 + (lane & 15)) * 80 +
                                           (kt * 16 + (lane >> 4) * 8) * 2);
                ldsm_x4(ah[mt], bufo + VB_AH + aoff);
                ldsm_x4(al[mt], bufo + VB_AL + aoff);
            }
            uint32_t bh[4][2], bl[4][2];
            #pragma unroll
            for (int p = 0; p < 2; p++) {
                uint32_t t[4];
                uint32_t boff = (uint32_t)((kt * 16 + (lane & 15)) * 272 +
                                           (wn * 32 + p * 16 + (lane >> 4) * 8) * 2);
                ldsm_x4t(t, bufo + VB_XH + boff);
                bh[2*p][0] = t[0]; bh[2*p][1] = t[1];
                bh[2*p+1][0] = t[2]; bh[2*p+1][1] = t[3];
                ldsm_x4t(t, bufo + VB_XL + boff);
                bl[2*p][0] = t[0]; bl[2*p][1] = t[1];
                bl[2*p+1][0] = t[2]; bl[2*p+1][1] = t[3];
            }
            #pragma unroll
            for (int nt = 0; nt < 4; nt++)
                #pragma unroll
                for (int mt = 0; mt < 2; mt++) {
                    mma_bf16(acc[mt][nt], ah[mt], bh[nt]);
                    mma_bf16(acc[mt][nt], ah[mt], bl[nt]);
                    mma_bf16(acc[mt][nt], al[mt], bh[nt]);
                }
        }
    }

    // ===== fused finisher epilogue =====
    __syncthreads();
    float* sT = (float*)sm;              // [128 d][68 k]

    #pragma unroll
    for (int mt = 0; mt < 2; mt++) {
        int k0 = wm * 32 + mt * 16 + (lane >> 2);
        float a0 = g_asum[b * KK + k0];
        float a8 = g_asum[b * KK + k0 + 8];
        float n20 = 0.f, n28 = 0.f;
        #pragma unroll
        for (int nt = 0; nt < 4; nt++) {
            int d = wn * 32 + nt * 8 + (lane & 3) * 2;
            const float* c2 = g_c2T + (size_t)k0 * DD + d0 + d;
            float2 c0 = *(const float2*)c2;
            float2 c8 = *(const float2*)(c2 + 8 * DD);
            float v00 = acc[mt][nt][0] - a0 * c0.x;
            float v01 = acc[mt][nt][1] - a0 * c0.y;
            float v80 = acc[mt][nt][2] - a8 * c8.x;
            float v81 = acc[mt][nt][3] - a8 * c8.y;
            sT[d * 68 + k0]           = v00;
            sT[(d + 1) * 68 + k0]     = v01;
            sT[d * 68 + k0 + 8]       = v80;
            sT[(d + 1) * 68 + k0 + 8] = v81;
            n20 += v00 * v00 + v01 * v01;
            n28 += v80 * v80 + v81 * v81;
        }
        n20 += __shfl_xor_sync(0xffffffffu, n20, 1);
        n20 += __shfl_xor_sync(0xffffffffu, n20, 2);
        n28 += __shfl_xor_sync(0xffffffffu, n28, 1);
        n28 += __shfl_xor_sync(0xffffffffu, n28, 2);
        if ((lane & 3) == 0) {
            atomicAdd(&g_norm2[b * KK + k0], n20);
            atomicAdd(&g_norm2[b * KK + k0 + 8], n28);
        }
    }
    __syncthreads();

    float* ob = out + ((size_t)b * DD + d0) * KK;
    #pragma unroll
    for (int j = 0; j < 8; j++) {
        int idx = tid + j * 256;
        int d = idx >> 4, u = idx & 15;
        float4 v = make_float4(sT[d * 68 + u * 4],     sT[d * 68 + u * 4 + 1],
                               sT[d * 68 + u * 4 + 2], sT[d * 68 + u * 4 + 3]);
        *(float4*)&ob[(size_t)d * KK + u * 4] = v;
    }
}

// ---------------------------------------------------------------------------
// Kernel 3: fused scale compute + in-place output scaling (1024 blocks)
// ---------------------------------------------------------------------------
__global__ __launch_bounds__(256) void k_out(float* __restrict__ out) {
    __shared__ float sInv[KK];
    __shared__ float sh[2];
    const int b = blockIdx.y, dg = blockIdx.x;   // dg 0..15
    const int t = threadIdx.x;
    if (t < KK) {
        float n2 = g_norm2[b * KK + t];
        float inv = 1.0f / fmaxf(sqrtf(n2), 1e-12f);
        float c = n2 * inv * inv;
        #pragma unroll
        for (int o = 16; o >= 1; o >>= 1) c += __shfl_xor_sync(0xffffffffu, c, o);
        if ((t & 31) == 0) sh[t >> 5] = c;
        sInv[t] = inv;
    }
    __syncthreads();
    float invt = 1.0f / fmaxf(sqrtf(sh[0] + sh[1]), 1e-12f);
    size_t base = (size_t)b * DD * KK + (size_t)dg * 2048;
    #pragma unroll
    for (int j = 0; j < 8; j++) {
        int i = t + j * 256;
        out[base + i] = out[base + i] * (sInv[i & 63] * invt);
    }
}

// ---------------------------------------------------------------------------
extern "C" void kernel_launch(void* const* d_in, const int* in_sizes, int n_in,
                              void* d_out, int out_size) {
    const float* x         = (const float*)d_in[0];
    const float* clusters  = (const float*)d_in[1];
    const float* clusters2 = (const float*)d_in[2];
    const float* bnw       = (const float*)d_in[3];
    const float* bnb       = (const float*)d_in[4];
    const float* rm        = (const float*)d_in[5];
    const float* rv        = (const float*)d_in[6];
    float* out = (float*)d_out;

    cudaFuncSetAttribute(k_logits_mma, cudaFuncAttributeMaxDynamicSharedMemorySize, L_SMEM);

    k_prep<<<(DD * KGC + 255) / 256, 256>>>(clusters, clusters2);
    dim3 g1(NN / 128, BB);
    k_logits_mma<<<g1, 256, L_SMEM>>>(x, bnw, bnb, rm, rv);
    dim3 g2(DD / 128, BB);
    k_vlad_mma<<<g2, 256>>>(x, out);
    dim3 g4(16, BB);
    k_out<<<g4, 256>>>(out);
}

// round 17
// speedup vs baseline: 1.0734x; 1.0029x over previous
#include <cuda_runtime.h>
#include <cuda_bf16.h>
#include <cstdint>

#define BB 64
#define NN 2048
#define DD 512
#define KK 64
#define KGC 80

// Scratch (device globals — no allocation allowed)
__device__ __align__(16) __nv_bfloat16 g_aThi[(size_t)BB * KK * NN]; // assignT hi [b][k][n]
__device__ __align__(16) __nv_bfloat16 g_aTlo[(size_t)BB * KK * NN]; // assignT lo
__device__ float g_asum[BB * KK];
__device__ float g_norm2[BB * KK];
__device__ unsigned g_cnt[BB];
__device__ __align__(16) __nv_bfloat16 g_cHi[DD * KGC];
__device__ __align__(16) __nv_bfloat16 g_cLo[DD * KGC];
__device__ float g_c2T[KK * DD];

// ===================== helpers =====================
__device__ __forceinline__ uint32_t smem_to_u32(const void* p) {
    uint32_t a;
    asm("{ .reg .u64 t; cvta.to.shared.u64 t, %1; cvt.u32.u64 %0, t; }" : "=r"(a) : "l"(p));
    return a;
}
__device__ __forceinline__ void mma_bf16(float* c, const uint32_t* a, const uint32_t* b) {
    asm volatile("mma.sync.aligned.m16n8k16.row.col.f32.bf16.bf16.f32 "
        "{%0,%1,%2,%3}, {%4,%5,%6,%7}, {%8,%9}, {%0,%1,%2,%3};"
        : "+f"(c[0]), "+f"(c[1]), "+f"(c[2]), "+f"(c[3])
        : "r"(a[0]), "r"(a[1]), "r"(a[2]), "r"(a[3]), "r"(b[0]), "r"(b[1]));
}
__device__ __forceinline__ void ldsm_x4(uint32_t* r, uint32_t addr) {
    asm volatile("ldmatrix.sync.aligned.m8n8.x4.shared.b16 {%0,%1,%2,%3}, [%4];"
        : "=r"(r[0]), "=r"(r[1]), "=r"(r[2]), "=r"(r[3]) : "r"(addr));
}
__device__ __forceinline__ void ldsm_x4t(uint32_t* r, uint32_t addr) {
    asm volatile("ldmatrix.sync.aligned.m8n8.x4.trans.shared.b16 {%0,%1,%2,%3}, [%4];"
        : "=r"(r[0]), "=r"(r[1]), "=r"(r[2]), "=r"(r[3]) : "r"(addr));
}
__device__ __forceinline__ void ldsm_x2t(uint32_t* r, uint32_t addr) {
    asm volatile("ldmatrix.sync.aligned.m8n8.x2.trans.shared.b16 {%0,%1}, [%2];"
        : "=r"(r[0]), "=r"(r[1]) : "r"(addr));
}
__device__ __forceinline__ void split2(float2 v, uint32_t& hi, uint32_t& lo) {
    __nv_bfloat162 h = __float22bfloat162_rn(v);
    float2 hf = __bfloat1622float2(h);
    __nv_bfloat162 l = __float22bfloat162_rn(make_float2(v.x - hf.x, v.y - hf.y));
    hi = *(uint32_t*)&h;
    lo = *(uint32_t*)&l;
}
#define CP_ASYNC16(dst, src) \
    asm volatile("cp.async.cg.shared.global [%0], [%1], 16;" :: "r"(dst), "l"(src) : "memory")
#define CP_COMMIT() asm volatile("cp.async.commit_group;" ::: "memory")
#define CP_WAIT0()  asm volatile("cp.async.wait_group 0;" ::: "memory")

// ---------------------------------------------------------------------------
// Kernel P: unified prep — cluster bf16 split + clusters2 transpose + zeroing
// ---------------------------------------------------------------------------
__global__ void k_prep(const float* __restrict__ clusters,
                       const float* __restrict__ clusters2) {
    int i = blockIdx.x * 256 + threadIdx.x;   // 0 .. 40959
    if (i < DD * KGC) {
        float v = clusters[i];
        __nv_bfloat16 h = __float2bfloat16(v);
        g_cHi[i] = h;
        g_cLo[i] = __float2bfloat16(v - __bfloat162float(h));
    }
    if (i < KK * DD) {
        int k = i >> 9, d = i & 511;
        g_c2T[i] = clusters2[d * KK + k];
    }
    if (i < BB * KK) { g_asum[i] = 0.0f; g_norm2[i] = 0.0f; }
    if (i < BB) g_cnt[i] = 0u;
}

// ---------------------------------------------------------------------------
// Kernel 1: logits GEMM (mma.sync bf16x3) + BN + softmax + a_sum + assignT
// (unchanged from R16)
// ---------------------------------------------------------------------------
#define LB_AH 0
#define LB_AL 10240
#define LB_BH 20480
#define LB_BL 26112
#define LB_SZ 31744
#define L_BN  63488
#define L_AS  64448
#define L_PM  65472
#define L_PS  66496
#define L_SMEM 67520

__global__ __launch_bounds__(256, 2) void k_logits_mma(
    const float* __restrict__ x,
    const float* __restrict__ bnw, const float* __restrict__ bnb,
    const float* __restrict__ rm, const float* __restrict__ rv)
{
    extern __shared__ __align__(16) char smem[];
    const int tid = threadIdx.x;
    const int lane = tid & 31, w = tid >> 5;
    const int wm = w & 3, wn = w >> 2;
    const int b = blockIdx.y, n0 = blockIdx.x * 128;
    const float* xb = x + ((size_t)b * NN + n0) * DD;
    uint32_t sb32 = smem_to_u32(smem);

    float* sScale = (float*)(smem + L_BN);
    float* sRm = sScale + 80;
    float* sBb = sScale + 160;
    if (tid < KGC) {
        sScale[tid] = bnw[tid] * rsqrtf(rv[tid] + 1e-5f);
        sRm[tid] = rm[tid];
        sBb[tid] = bnb[tid];
    }

    float acc[2][5][4];
    #pragma unroll
    for (int mt = 0; mt < 2; mt++)
        #pragma unroll
        for (int nt = 0; nt < 5; nt++)
            #pragma unroll
            for (int e = 0; e < 4; e++) acc[mt][nt][e] = 0.f;

    const int xr_r = tid >> 3, xr_u = tid & 7;
    const int br0 = tid / 10, bc0 = tid - br0 * 10;
    const int bidx1 = tid + 256;
    const int u1 = bidx1 >= 320 ? bidx1 - 320 : bidx1;
    const int barr1 = bidx1 >= 320;
    const int br1 = u1 / 10, bc1 = u1 - br1 * 10;
    const int u2 = tid + 512 - 320;
    const int br2 = u2 / 10, bc2 = u2 - br2 * 10;
    const bool bp2 = tid < 128;

    auto cp_b = [&](int stage) {
        uint32_t base = sb32 + (uint32_t)((stage & 1) * LB_SZ);
        const __nv_bfloat16* s0 = g_cHi + (size_t)(stage * 32 + br0) * KGC + bc0 * 8;
        CP_ASYNC16(base + LB_BH + br0 * 176 + bc0 * 16, s0);
        const __nv_bfloat16* s1 = (barr1 ? g_cLo : g_cHi) + (size_t)(stage * 32 + br1) * KGC + bc1 * 8;
        CP_ASYNC16(base + (barr1 ? LB_BL : LB_BH) + br1 * 176 + bc1 * 16, s1);
        if (bp2) {
            const __nv_bfloat16* s2 = g_cLo + (size_t)(stage * 32 + br2) * KGC + bc2 * 8;
            CP_ASYNC16(base + LB_BL + br2 * 176 + bc2 * 16, s2);
        }
        CP_COMMIT();
    };

    float4 xr[4];
    cp_b(0);
    #pragma unroll
    for (int j = 0; j < 4; j++)
        xr[j] = *(const float4*)&xb[(size_t)(xr_r + j * 32) * DD + xr_u * 4];

    for (int dt = 0; dt < 16; dt++) {
        char* buf = smem + (dt & 1) * LB_SZ;
        #pragma unroll
        for (int j = 0; j < 4; j++) {
            uint32_t h0, l0, h1, l1;
            split2(make_float2(xr[j].x, xr[j].y), h0, l0);
            split2(make_float2(xr[j].z, xr[j].w), h1, l1);
            int off = (xr_r + j * 32) * 80 + xr_u * 8;
            *(uint2*)(buf + LB_AH + off) = make_uint2(h0, h1);
            *(uint2*)(buf + LB_AL + off) = make_uint2(l0, l1);
        }
        if (dt < 15) {
            #pragma unroll
            for (int j = 0; j < 4; j++)
                xr[j] = *(const float4*)&xb[(size_t)(xr_r + j * 32) * DD +
                                            (dt + 1) * 32 + xr_u * 4];
        }
        CP_WAIT0();
        __syncthreads();
        if (dt < 15) cp_b(dt + 1);

        uint32_t bufo = sb32 + (uint32_t)((dt & 1) * LB_SZ);
        #pragma unroll
        for (int kt = 0; kt < 2; kt++) {
            uint32_t ah[2][4], al[2][4];
            #pragma unroll
            for (int mt = 0; mt < 2; mt++) {
                uint32_t aoff = (uint32_t)((wm * 32 + mt * 16 + (lane & 15)) * 80 +
                                           (kt * 16 + (lane >> 4) * 8) * 2);
                ldsm_x4(ah[mt], bufo + LB_AH + aoff);
                ldsm_x4(al[mt], bufo + LB_AL + aoff);
            }
            uint32_t bh[5][2], bl[5][2];
            #pragma unroll
            for (int p = 0; p < 2; p++) {
                uint32_t t[4];
                uint32_t boff = (uint32_t)((kt * 16 + (lane & 15)) * 176 +
                                           (wn * 40 + p * 16 + (lane >> 4) * 8) * 2);
                ldsm_x4t(t, bufo + LB_BH + boff);
                bh[2*p][0] = t[0]; bh[2*p][1] = t[1];
                bh[2*p+1][0] = t[2]; bh[2*p+1][1] = t[3];
                ldsm_x4t(t, bufo + LB_BL + boff);
                bl[2*p][0] = t[0]; bl[2*p][1] = t[1];
                bl[2*p+1][0] = t[2]; bl[2*p+1][1] = t[3];
            }
            {
                uint32_t boff = (uint32_t)((kt * 16 + (lane & 15)) * 176 + (wn * 40 + 32) * 2);
                ldsm_x2t(bh[4], bufo + LB_BH + boff);
                ldsm_x2t(bl[4], bufo + LB_BL + boff);
            }
            #pragma unroll
            for (int nt = 0; nt < 5; nt++)
                #pragma unroll
                for (int mt = 0; mt < 2; mt++) {
                    mma_bf16(acc[mt][nt], ah[mt], bh[nt]);
                    mma_bf16(acc[mt][nt], ah[mt], bl[nt]);
                    mma_bf16(acc[mt][nt], al[mt], bh[nt]);
                }
        }
    }
    __syncthreads();

    // ---- BN affine ----
    #pragma unroll
    for (int nt = 0; nt < 5; nt++) {
        int c0 = wn * 40 + nt * 8 + (lane & 3) * 2;
        float s0 = sScale[c0], s1 = sScale[c0 + 1];
        float m0 = sRm[c0],    m1 = sRm[c0 + 1];
        float q0 = sBb[c0],    q1 = sBb[c0 + 1];
        #pragma unroll
        for (int mt = 0; mt < 2; mt++) {
            acc[mt][nt][0] = (acc[mt][nt][0] - m0) * s0 + q0;
            acc[mt][nt][1] = (acc[mt][nt][1] - m1) * s1 + q1;
            acc[mt][nt][2] = (acc[mt][nt][2] - m0) * s0 + q0;
            acc[mt][nt][3] = (acc[mt][nt][3] - m1) * s1 + q1;
        }
    }

    // ---- softmax: 2-pass smem reduction across N-warps ----
    float* sPM = (float*)(smem + L_PM);
    float* sPS = (float*)(smem + L_PS);
    float* sOut = (float*)smem;

    #pragma unroll
    for (int h = 0; h < 4; h++) {
        int mt = h >> 1, hh = h & 1;
        float mx = -3.4e38f;
        #pragma unroll
        for (int nt = 0; nt < 5; nt++)
            mx = fmaxf(mx, fmaxf(acc[mt][nt][hh * 2], acc[mt][nt][hh * 2 + 1]));
        mx = fmaxf(mx, __shfl_xor_sync(0xffffffffu, mx, 1));
        mx = fmaxf(mx, __shfl_xor_sync(0xffffffffu, mx, 2));
        int row = wm * 32 + mt * 16 + hh * 8 + (lane >> 2);
        if ((lane & 3) == 0) sPM[row * 2 + wn] = mx;
    }
    __syncthreads();
    #pragma unroll
    for (int h = 0; h < 4; h++) {
        int mt = h >> 1, hh = h & 1;
        int row = wm * 32 + mt * 16 + hh * 8 + (lane >> 2);
        float m = fmaxf(sPM[row * 2], sPM[row * 2 + 1]);
        float sum = 0.f;
        #pragma unroll
        for (int nt = 0; nt < 5; nt++) {
            float e0 = __expf(acc[mt][nt][hh * 2] - m);
            float e1 = __expf(acc[mt][nt][hh * 2 + 1] - m);
            acc[mt][nt][hh * 2] = e0;
            acc[mt][nt][hh * 2 + 1] = e1;
            sum += e0 + e1;
        }
        sum += __shfl_xor_sync(0xffffffffu, sum, 1);
        sum += __shfl_xor_sync(0xffffffffu, sum, 2);
        if ((lane & 3) == 0) sPS[row * 2 + wn] = sum;
    }
    __syncthreads();
    const int ntmax = wn ? 3 : 5;
    #pragma unroll
    for (int h = 0; h < 4; h++) {
        int mt = h >> 1, hh = h & 1;
        int row = wm * 32 + mt * 16 + hh * 8 + (lane >> 2);
        float inv = 1.0f / (sPS[row * 2] + sPS[row * 2 + 1]);
        #pragma unroll
        for (int nt = 0; nt < 5; nt++) {
            if (nt < ntmax) {
                int col = wn * 40 + nt * 8 + (lane & 3) * 2;
                float2 v = make_float2(acc[mt][nt][hh * 2] * inv,
                                       acc[mt][nt][hh * 2 + 1] * inv);
                *(float2*)&sOut[row * 66 + col] = v;
            }
        }
    }
    __syncthreads();

    // ---- a_sum ----
    float* sAs = (float*)(smem + L_AS);
    {
        int k = tid & 63, qq = tid >> 6;
        float s = 0.f;
        #pragma unroll 8
        for (int r = qq * 32; r < qq * 32 + 32; r++) s += sOut[r * 66 + k];
        sAs[qq * 64 + k] = s;
    }
    __syncthreads();
    if (tid < KK)
        atomicAdd(&g_asum[b * KK + tid],
                  sAs[tid] + sAs[64 + tid] + sAs[128 + tid] + sAs[192 + tid]);

    // ---- assignment^T bf16 hi/lo, packed bf16x2 stores ----
    {
        int np = (tid & 63) * 2;
        int kh = (tid >> 6) * 16;
        uint32_t* aThi = (uint32_t*)(g_aThi + (size_t)b * KK * NN + n0 + np);
        uint32_t* aTlo = (uint32_t*)(g_aTlo + (size_t)b * KK * NN + n0 + np);
        #pragma unroll 4
        for (int kk2 = 0; kk2 < 16; kk2++) {
            int k = kh + kk2;
            float v0 = sOut[np * 66 + k];
            float v1 = sOut[(np + 1) * 66 + k];
            uint32_t hi, lo;
            split2(make_float2(v0, v1), hi, lo);
            aThi[(size_t)k * (NN / 2)] = hi;
            aTlo[(size_t)k * (NN / 2)] = lo;
        }
    }
}

// ---------------------------------------------------------------------------
// Kernel 2: vlad GEMM + fused finisher + counter-synced FINAL SCALING.
// All 256 CTAs co-resident (grid 256 <= 296 slots) -> spin is deadlock-free.
// ---------------------------------------------------------------------------
#define VB_XH 0
#define VB_XL 8704
#define VB_AH 17408
#define VB_AL 22528
#define VB_SZ 27648

__global__ __launch_bounds__(256, 2) void k_vlad_mma(const float* __restrict__ x,
                                                     float* __restrict__ out)
{
    __shared__ __align__(16) char sm[2 * VB_SZ];
    __shared__ float sInv[KK];
    __shared__ float sh2[2];
    const int tid = threadIdx.x, lane = tid & 31, w = tid >> 5;
    const int wm = w & 1, wn = w >> 1;
    const int b = blockIdx.y, d0 = blockIdx.x * 128;
    const float* xb = x + (size_t)b * NN * DD + d0;
    const __nv_bfloat16* aThi = g_aThi + (size_t)b * KK * NN;
    const __nv_bfloat16* aTlo = g_aTlo + (size_t)b * KK * NN;
    uint32_t sb32 = smem_to_u32(sm);

    float acc[2][4][4];
    #pragma unroll
    for (int mt = 0; mt < 2; mt++)
        #pragma unroll
        for (int nt = 0; nt < 4; nt++)
            #pragma unroll
            for (int e = 0; e < 4; e++) acc[mt][nt][e] = 0.f;

    const int xr_r = tid >> 5, xr_u = tid & 31;
    const int ar_r = tid >> 2, ar_u = tid & 3;

    auto cp_a = [&](int nc) {
        const int nbase = nc * 32;
        uint32_t base = sb32 + (uint32_t)((nc & 1) * VB_SZ);
        size_t ge = (size_t)ar_r * NN + nbase + ar_u * 8;
        CP_ASYNC16(base + VB_AH + ar_r * 80 + ar_u * 16, aThi + ge);
        CP_ASYNC16(base + VB_AL + ar_r * 80 + ar_u * 16, aTlo + ge);
        CP_COMMIT();
    };

    float4 xr[4];
    cp_a(0);
    #pragma unroll
    for (int j = 0; j < 4; j++)
        xr[j] = *(const float4*)&xb[(size_t)(xr_r + j * 8) * DD + xr_u * 4];

    for (int nc = 0; nc < 64; nc++) {
        char* buf = sm + (nc & 1) * VB_SZ;
        #pragma unroll
        for (int j = 0; j < 4; j++) {
            uint32_t h0, l0, h1, l1;
            split2(make_float2(xr[j].x, xr[j].y), h0, l0);
            split2(make_float2(xr[j].z, xr[j].w), h1, l1);
            int off = (xr_r + j * 8) * 272 + xr_u * 8;
            *(uint2*)(buf + VB_XH + off) = make_uint2(h0, h1);
            *(uint2*)(buf + VB_XL + off) = make_uint2(l0, l1);
        }
        if (nc < 63) {
            const int nbase = (nc + 1) * 32;
            #pragma unroll
            for (int j = 0; j < 4; j++)
                xr[j] = *(const float4*)&xb[(size_t)(nbase + xr_r + j * 8) * DD + xr_u * 4];
        }
        CP_WAIT0();
        __syncthreads();
        if (nc < 63) cp_a(nc + 1);

        uint32_t bufo = sb32 + (uint32_t)((nc & 1) * VB_SZ);
        #pragma unroll
        for (int kt = 0; kt < 2; kt++) {
            uint32_t ah[2][4], al[2][4];
            #pragma unroll
            for (int mt = 0; mt < 2; mt++) {
                uint32_t aoff = (uint32_t)((wm * 32 + mt * 16 + (lane & 15)) * 80 +
                                           (kt * 16 + (lane >> 4) * 8) * 2);
                ldsm_x4(ah[mt], bufo + VB_AH + aoff);
                ldsm_x4(al[mt], bufo + VB_AL + aoff);
            }
            uint32_t bh[4][2], bl[4][2];
            #pragma unroll
            for (int p = 0; p < 2; p++) {
                uint32_t t[4];
                uint32_t boff = (uint32_t)((kt * 16 + (lane & 15)) * 272 +
                                           (wn * 32 + p * 16 + (lane >> 4) * 8) * 2);
                ldsm_x4t(t, bufo + VB_XH + boff);
                bh[2*p][0] = t[0]; bh[2*p][1] = t[1];
                bh[2*p+1][0] = t[2]; bh[2*p+1][1] = t[3];
                ldsm_x4t(t, bufo + VB_XL + boff);
                bl[2*p][0] = t[0]; bl[2*p][1] = t[1];
                bl[2*p+1][0] = t[2]; bl[2*p+1][1] = t[3];
            }
            #pragma unroll
            for (int nt = 0; nt < 4; nt++)
                #pragma unroll
                for (int mt = 0; mt < 2; mt++) {
                    mma_bf16(acc[mt][nt], ah[mt], bh[nt]);
                    mma_bf16(acc[mt][nt], ah[mt], bl[nt]);
                    mma_bf16(acc[mt][nt], al[mt], bh[nt]);
                }
        }
    }

    // ===== fused finisher: subtract, norm2 atomics, stage sT =====
    __syncthreads();
    float* sT = (float*)sm;              // [128 d][68 k]

    #pragma unroll
    for (int mt = 0; mt < 2; mt++) {
        int k0 = wm * 32 + mt * 16 + (lane >> 2);
        float a0 = g_asum[b * KK + k0];
        float a8 = g_asum[b * KK + k0 + 8];
        float n20 = 0.f, n28 = 0.f;
        #pragma unroll
        for (int nt = 0; nt < 4; nt++) {
            int d = wn * 32 + nt * 8 + (lane & 3) * 2;
            const float* c2 = g_c2T + (size_t)k0 * DD + d0 + d;
            float2 c0 = *(const float2*)c2;
            float2 c8 = *(const float2*)(c2 + 8 * DD);
            float v00 = acc[mt][nt][0] - a0 * c0.x;
            float v01 = acc[mt][nt][1] - a0 * c0.y;
            float v80 = acc[mt][nt][2] - a8 * c8.x;
            float v81 = acc[mt][nt][3] - a8 * c8.y;
            sT[d * 68 + k0]           = v00;
            sT[(d + 1) * 68 + k0]     = v01;
            sT[d * 68 + k0 + 8]       = v80;
            sT[(d + 1) * 68 + k0 + 8] = v81;
            n20 += v00 * v00 + v01 * v01;
            n28 += v80 * v80 + v81 * v81;
        }
        n20 += __shfl_xor_sync(0xffffffffu, n20, 1);
        n20 += __shfl_xor_sync(0xffffffffu, n20, 2);
        n28 += __shfl_xor_sync(0xffffffffu, n28, 1);
        n28 += __shfl_xor_sync(0xffffffffu, n28, 2);
        if ((lane & 3) == 0) {
            atomicAdd(&g_norm2[b * KK + k0], n20);
            atomicAdd(&g_norm2[b * KK + k0 + 8], n28);
        }
    }

    // ===== counter rendezvous across the 4 CTAs of this b =====
    __threadfence();
    __syncthreads();
    if (tid == 0) {
        atomicAdd(&g_cnt[b], 1u);
        while (atomicAdd(&g_cnt[b], 0u) < 4u) { }
    }
    __syncthreads();

    // ===== compute scales from final norm2, write scaled output =====
    if (tid < KK) {
        float n2 = __ldcg(&g_norm2[b * KK + tid]);
        float inv = 1.0f / fmaxf(sqrtf(n2), 1e-12f);
        float c = n2 * inv * inv;
        #pragma unroll
        for (int o = 16; o >= 1; o >>= 1) c += __shfl_xor_sync(0xffffffffu, c, o);
        if ((tid & 31) == 0) sh2[tid >> 5] = c;
        sInv[tid] = inv;
    }
    __syncthreads();
    float invt = 1.0f / fmaxf(sqrtf(sh2[0] + sh2[1]), 1e-12f);

    float* ob = out + ((size_t)b * DD + d0) * KK;
    #pragma unroll
    for (int j = 0; j < 8; j++) {
        int idx = tid + j * 256;
        int d = idx >> 4, u = idx & 15;
        int kb = u * 4;
        float4 v = make_float4(sT[d * 68 + kb]     * (sInv[kb]     * invt),
                               sT[d * 68 + kb + 1] * (sInv[kb + 1] * invt),
                               sT[d * 68 + kb + 2] * (sInv[kb + 2] * invt),
                               sT[d * 68 + kb + 3] * (sInv[kb + 3] * invt));
        *(float4*)&ob[(size_t)d * KK + u * 4] = v;
    }
}

// ---------------------------------------------------------------------------
extern "C" void kernel_launch(void* const* d_in, const int* in_sizes, int n_in,
                              void* d_out, int out_size) {
    const float* x         = (const float*)d_in[0];
    const float* clusters  = (const float*)d_in[1];
    const float* clusters2 = (const float*)d_in[2];
    const float* bnw       = (const float*)d_in[3];
    const float* bnb       = (const float*)d_in[4];
    const float* rm        = (const float*)d_in[5];
    const float* rv        = (const float*)d_in[6];
    float* out = (float*)d_out;

    cudaFuncSetAttribute(k_logits_mma, cudaFuncAttributeMaxDynamicSharedMemorySize, L_SMEM);

    k_prep<<<(DD * KGC + 255) / 256, 256>>>(clusters, clusters2);
    dim3 g1(NN / 128, BB);
    k_logits_mma<<<g1, 256, L_SMEM>>>(x, bnw, bnb, rm, rv);
    dim3 g2(DD / 128, BB);
    k_vlad_mma<<<g2, 256>>>(x, out);
}